// round 13
// baseline (speedup 1.0000x reference)
#include <cuda_runtime.h>
#include <cuda_fp16.h>
#include <cstdint>
#include <math.h>

// Problem constants
#define CB 4
#define CS 2048
#define CE 1024
#define CH 4
#define CD 256
#define CBH 16      // B*H
#define CM 8192     // B*S tokens

// ---------------- f32 scratch ----------------
__device__ float g_v   [(size_t)CM * CE];
__device__ float g_sq  [(size_t)CM * CE];
__device__ float g_sk  [(size_t)CM * CE];
__device__ float g_amem[(size_t)CM * CE];
__device__ float g_U   [(size_t)CM * CE];
__device__ float g_P   [(size_t)CBH * CS * CS];   // f32 logits
__device__ float g_denq[CBH * CS];
__device__ float g_denk[CBH * CS];
__device__ float g_zpart[CBH * 8 * CD];
__device__ float g_memp[(size_t)4 * CBH * CD * CD];  // split-K partials

// ---------------- fp16 scratch (uint4-typed for 16B alignment) ----------------
__device__ uint4 g_xh  [(size_t)CM * CE / 8];
__device__ uint4 g_xl  [(size_t)CM * CE / 8];
__device__ uint4 g_qh  [(size_t)CM * CE / 8];
__device__ uint4 g_ql  [(size_t)CM * CE / 8];
__device__ uint4 g_kh  [(size_t)CM * CE / 8];
__device__ uint4 g_kl  [(size_t)CM * CE / 8];
__device__ uint4 g_mh  [(size_t)CM * CE / 8];   // PV mix split
__device__ uint4 g_ml  [(size_t)CM * CE / 8];
__device__ uint4 g_sqh [(size_t)CM * CE / 8];
__device__ uint4 g_sql [(size_t)CM * CE / 8];
__device__ uint4 g_skh [(size_t)CM * CE / 8];
__device__ uint4 g_skl [(size_t)CM * CE / 8];
__device__ uint4 g_wqh [(size_t)CE * CE / 8];
__device__ uint4 g_wql [(size_t)CE * CE / 8];
__device__ uint4 g_wkh [(size_t)CE * CE / 8];
__device__ uint4 g_wkl [(size_t)CE * CE / 8];
__device__ uint4 g_wvh [(size_t)CE * CE / 8];
__device__ uint4 g_wvl [(size_t)CE * CE / 8];
__device__ uint4 g_woh [(size_t)CE * CE / 8];
__device__ uint4 g_wol [(size_t)CE * CE / 8];
__device__ uint4 g_ph  [(size_t)CBH * CS * CS / 8];  // softmax probs hi
__device__ uint4 g_pl  [(size_t)CBH * CS * CS / 8];  // softmax probs lo
__device__ uint4 g_vth [(size_t)CBH * CD * CS / 8];  // v^T per head
__device__ uint4 g_vtl [(size_t)CBH * CD * CS / 8];
__device__ uint4 g_skth[(size_t)CBH * CD * CS / 8];  // sk^T per head
__device__ uint4 g_sktl[(size_t)CBH * CD * CS / 8];
__device__ uint4 g_uth [(size_t)CBH * CD * CS / 8];  // U^T per head
__device__ uint4 g_utl [(size_t)CBH * CD * CS / 8];
__device__ uint4 g_mth [(size_t)CH * CD * CD / 8];   // mem^T per head
__device__ uint4 g_mtl [(size_t)CH * CD * CD / 8];

// ======================= helpers =======================
__device__ __forceinline__ uint32_t smem_u32(const void* p) {
    uint32_t a;
    asm("{ .reg .u64 t; cvta.to.shared.u64 t, %1; cvt.u32.u64 %0, t; }" : "=r"(a) : "l"(p));
    return a;
}
#define CPA16(dst, src) \
    asm volatile("cp.async.cg.shared.global [%0], [%1], 16;" :: "r"(dst), "l"(src))
#define CP_COMMIT() asm volatile("cp.async.commit_group;")
#define CP_WAIT2()  asm volatile("cp.async.wait_group 2;")

#define LDSM4(r, addr) \
    asm volatile("ldmatrix.sync.aligned.m8n8.x4.shared.b16 {%0,%1,%2,%3}, [%4];" \
        : "=r"((r)[0]), "=r"((r)[1]), "=r"((r)[2]), "=r"((r)[3]) : "r"(addr))

#define MMA16816(d, a, b0, b1) \
    asm volatile("mma.sync.aligned.m16n8k16.row.col.f32.f16.f16.f32 " \
        "{%0,%1,%2,%3}, {%4,%5,%6,%7}, {%8,%9}, {%0,%1,%2,%3};" \
        : "+f"((d)[0]), "+f"((d)[1]), "+f"((d)[2]), "+f"((d)[3]) \
        : "r"((a)[0]), "r"((a)[1]), "r"((a)[2]), "r"((a)[3]), "r"(b0), "r"(b1))

__device__ __forceinline__ __half2 split_hi2(float a, float b, __half2& lo) {
    const __half h0 = __float2half_rn(a), h1 = __float2half_rn(b);
    lo = __halves2half2(__float2half_rn(a - __half2float(h0)),
                        __float2half_rn(b - __half2float(h1)));
    return __halves2half2(h0, h1);
}
__device__ __forceinline__ float elu1f(float x) {
    return (x > 0.f) ? x + 1.f : __expf(x);
}

// ===========================================================================
// HMMA split-fp16 GEMM: C[M,N] = A·B^T. A:[rows,K] K-major lda, B:[cols,K] ldb.
// NTERM=3: Ah·Bh + Ah·Bl + Al·Bh. NTERM=2: Ah·Bh + Al·Bh (B hi-only).
// Tile 128x128, KT=64, 3-stage cp.async. 8 warps (4M x 2N). R5-proven config.
// EPI: 0 f32 | 1 f32+bias | 2 QK causal (skip masked, z=bh) | 3 PV gate-mix ->
//      split out | 4 split out | 5 A_mem acc/den | 6 U=v-acc/den |
//      9 Q/K proj: q split + sigma f32 + sigma split | 10 split-K partial f32
// ===========================================================================
template <int EPI, int NTERM>
__global__ void __launch_bounds__(256, 1)
hmma_gemm(const __half* __restrict__ Ah, const __half* __restrict__ Al,
          const __half* __restrict__ Bh, const __half* __restrict__ Bl,
          float* __restrict__ Cg, __half* __restrict__ Oh, __half* __restrict__ Ol,
          __half* __restrict__ Sh, __half* __restrict__ Sl,
          int K, int lda, int ldb, int ldc,
          const float* __restrict__ aux0, const float* __restrict__ aux1)
{
    const int m0 = blockIdx.y * 128, n0 = blockIdx.x * 128;
    const int z = blockIdx.z;
    constexpr int SS = (NTERM == 3) ? 65536 : 49152;   // stage stride
    size_t offA = 0, offB = 0, offC = 0;
    const float* amem = nullptr;
    const float* den  = nullptr;
    const float* vsrc = nullptr;
    float gate = 0.f, omg = 0.f;
    int Keff = K;
    if (EPI == 2) {
        if (n0 >= m0 + 128) return;   // fully masked tile: softmax never reads it
        const int b = z / CH, h = z % CH;
        offA = offB = (size_t)b * CS * CE + (size_t)h * CD;
        offC = (size_t)z * CS * CS;
    } else if (EPI == 3) {
        const int b = z / CH, h = z % CH;
        offA = (size_t)z * CS * CS;
        offB = (size_t)z * CD * CS;
        offC = (size_t)b * CS * CE + (size_t)h * CD;
        amem = aux0 + offC;
        gate = 1.f / (1.f + __expf(-aux1[h]));
        omg  = 1.f - gate;
        Keff = min(K, m0 + 128);      // probs zero beyond row block
    } else if (EPI == 5 || EPI == 6) {
        const int b = z / CH, h = z % CH;
        offA = (size_t)b * CS * CE + (size_t)h * CD;
        offB = (size_t)h * CD * CD;
        offC = offA;
        den  = aux0 + (size_t)z * CS;
        if (EPI == 6) vsrc = aux1 + offC;
    } else if (EPI == 10) {
        // split-K mem-update partial: z = bh*4 + chunk, K = 512 per chunk
        const int bh = z >> 2, chunk = z & 3;
        offA = (size_t)bh * CD * CS + (size_t)chunk * 512;
        offB = offA;
        offC = (size_t)z * CD * CD;
    }

    extern __shared__ char dsm_raw[];
    char* base = dsm_raw + ((1024 - (smem_u32(dsm_raw) & 1023)) & 1023);
    const uint32_t sb = smem_u32(base);

    const int tid = threadIdx.x;
    const int wid = tid >> 5, lane = tid & 31;
    const int wm = wid & 3, wn = wid >> 2;

    const __half* pAh = Ah + offA;
    const __half* pAl = Al + offA;
    const __half* pBh = Bh + offB;
    const __half* pBl = Bl + offB;

    auto load_stage = [&](int kt, int stage) {
        const int k0 = kt * 64;
        const uint32_t sbase = sb + stage * SS;
        constexpr int NIT = (NTERM == 3) ? 16 : 12;
#pragma unroll
        for (int it = 0; it < NIT; it++) {
            const int mat = it >> 2;
            const int rem = tid + (it & 3) * 256;
            const int row = rem >> 3, k8 = rem & 7;
            const uint32_t dst = sbase + mat * 16384 + row * 128 + ((k8 ^ (row & 7)) << 4);
            const __half* src;
            if (mat == 0)      src = pAh + (size_t)(m0 + row) * lda + k0 + k8 * 8;
            else if (mat == 1) src = pAl + (size_t)(m0 + row) * lda + k0 + k8 * 8;
            else if (mat == 2) src = pBh + (size_t)(n0 + row) * ldb + k0 + k8 * 8;
            else               src = pBl + (size_t)(n0 + row) * ldb + k0 + k8 * 8;
            CPA16(dst, src);
        }
    };

    float acc[2][8][4];
#pragma unroll
    for (int mi = 0; mi < 2; mi++)
#pragma unroll
        for (int nj = 0; nj < 8; nj++)
#pragma unroll
            for (int r = 0; r < 4; r++) acc[mi][nj][r] = 0.f;

    const int nkt = Keff / 64;   // >= 2 everywhere

    load_stage(0, 0); CP_COMMIT();
    load_stage(1, 1); CP_COMMIT();
    load_stage(2, 2); CP_COMMIT();   // may prefetch past Keff: in-bounds, unused

    int buf = 0;
    for (int kt = 0; kt < nkt; kt++) {
        CP_WAIT2();
        __syncthreads();
        const uint32_t sA = sb + buf * SS;
        const uint32_t sB = sA + 32768;
#pragma unroll
        for (int ks = 0; ks < 4; ks++) {
            uint32_t af[2][2][4];
#pragma unroll
            for (int mi = 0; mi < 2; mi++) {
                const int row = wm * 32 + mi * 16 + (lane & 15);
                const int k8 = ks * 2 + (lane >> 4);
                const uint32_t off = row * 128 + ((k8 ^ (row & 7)) << 4);
                LDSM4(af[mi][0], sA + off);
                LDSM4(af[mi][1], sA + 16384 + off);
            }
            uint32_t bf[4][2][4];
#pragma unroll
            for (int np = 0; np < 4; np++) {
                const int n = wn * 64 + np * 16 + (lane & 7) + ((lane >> 4) << 3);
                const int k8 = ks * 2 + ((lane >> 3) & 1);
                const uint32_t off = n * 128 + ((k8 ^ (n & 7)) << 4);
                LDSM4(bf[np][0], sB + off);
                if (NTERM == 3) LDSM4(bf[np][1], sB + 16384 + off);
            }
#pragma unroll
            for (int mi = 0; mi < 2; mi++)
#pragma unroll
                for (int nj = 0; nj < 8; nj++) {
                    const uint32_t* bh = &bf[nj >> 1][0][(nj & 1) * 2];
                    MMA16816(acc[mi][nj], af[mi][0], bh[0], bh[1]);
                    if (NTERM == 3) {
                        const uint32_t* bl = &bf[nj >> 1][1][(nj & 1) * 2];
                        MMA16816(acc[mi][nj], af[mi][0], bl[0], bl[1]);
                    }
                    MMA16816(acc[mi][nj], af[mi][1], bh[0], bh[1]);
                }
        }
        __syncthreads();
        if (kt + 3 < nkt) load_stage(kt + 3, buf);
        CP_COMMIT();
        buf = (buf == 2) ? 0 : buf + 1;
    }

    // ---- epilogue ----
#pragma unroll
    for (int mi = 0; mi < 2; mi++) {
#pragma unroll
        for (int nj = 0; nj < 8; nj++) {
            const int gr0 = m0 + wm * 32 + mi * 16 + (lane >> 2);
            const int gc  = n0 + wn * 64 + nj * 8 + (lane & 3) * 2;
#pragma unroll
            for (int hf = 0; hf < 2; hf++) {
                const int gr = gr0 + hf * 8;
                const size_t idx = (size_t)gr * ldc + gc;
                float d0 = acc[mi][nj][hf * 2], d1 = acc[mi][nj][hf * 2 + 1];
                if (EPI == 9) {
                    // q/k split out + sigma (f32 + split)
                    __half2 lo;
                    const __half2 hi = split_hi2(d0, d1, lo);
                    *(__half2*)(Oh + idx) = hi;
                    *(__half2*)(Ol + idx) = lo;
                    const float s0 = elu1f(d0), s1 = elu1f(d1);
                    *(float2*)(Cg + idx) = make_float2(s0, s1);
                    __half2 slo;
                    const __half2 shi = split_hi2(s0, s1, slo);
                    *(__half2*)(Sh + idx) = shi;
                    *(__half2*)(Sl + idx) = slo;
                    continue;
                }
                if (EPI == 1) { d0 += aux0[gc]; d1 += aux0[gc + 1]; }
                if (EPI == 3) {
                    d0 = gate * amem[idx] + omg * d0;
                    d1 = gate * amem[idx + 1] + omg * d1;
                }
                if (EPI == 5) {
                    const float r = 1.f / (den[gr] + 1e-6f);
                    d0 *= r; d1 *= r;
                }
                if (EPI == 6) {
                    const float r = 1.f / (den[gr] + 1e-6f);
                    d0 = vsrc[idx] - d0 * r;
                    d1 = vsrc[idx + 1] - d1 * r;
                }
                if (EPI == 3 || EPI == 4) {
                    __half2 lo;
                    const __half2 hi = split_hi2(d0, d1, lo);
                    *(__half2*)(Oh + offC + idx) = hi;
                    *(__half2*)(Ol + offC + idx) = lo;
                } else {
                    *(float2*)(Cg + offC + idx) = make_float2(d0, d1);
                }
            }
        }
    }
}

// ===========================================================================
// split / transpose-split kernels
// ===========================================================================
__global__ void split_kernel(const float4* __restrict__ in,
                             uint2* __restrict__ hi, uint2* __restrict__ lo)
{
    const size_t i = (size_t)blockIdx.x * blockDim.x + threadIdx.x;
    const float4 v = in[i];
    __half2 l0, l1;
    const __half2 h0 = split_hi2(v.x, v.y, l0);
    const __half2 h1 = split_hi2(v.z, v.w, l1);
    uint2 uh, ul;
    uh.x = *(const uint32_t*)&h0; uh.y = *(const uint32_t*)&h1;
    ul.x = *(const uint32_t*)&l0; ul.y = *(const uint32_t*)&l1;
    hi[i] = uh; lo[i] = ul;
}

// W[K,N] (1024x1024) -> Wt_hi/lo[N,K]
__global__ void splitT_kernel(const float* __restrict__ W,
                              __half* __restrict__ th, __half* __restrict__ tl)
{
    __shared__ float t[32][33];
    const int n0 = blockIdx.x * 32, k0 = blockIdx.y * 32;
    const int tx = threadIdx.x, ty = threadIdx.y;
#pragma unroll
    for (int i = 0; i < 4; i++)
        t[ty + i * 8][tx] = W[(size_t)(k0 + ty + i * 8) * CE + n0 + tx];
    __syncthreads();
#pragma unroll
    for (int i = 0; i < 4; i++) {
        const float v = t[tx][ty + i * 8];
        const __half h = __float2half_rn(v);
        const size_t o = (size_t)(n0 + ty + i * 8) * CE + k0 + tx;
        th[o] = h;
        tl[o] = __float2half_rn(v - __half2float(h));
    }
}

// src [B,S,E] head slice -> dst [bh, D, S] fp16 hi/lo (transpose + split)
__global__ void tsplit_head_kernel(const float* __restrict__ src,
                                   __half* __restrict__ th, __half* __restrict__ tl)
{
    __shared__ float t[32][33];
    const int z = blockIdx.z, b = z / CH, h = z % CH;
    const int s0 = blockIdx.x * 32, d0 = blockIdx.y * 32;
    const int tx = threadIdx.x, ty = threadIdx.y;
#pragma unroll
    for (int i = 0; i < 4; i++)
        t[ty + i * 8][tx] = src[(size_t)(b * CS + s0 + ty + i * 8) * CE + h * CD + d0 + tx];
    __syncthreads();
#pragma unroll
    for (int i = 0; i < 4; i++) {
        const float vv = t[tx][ty + i * 8];
        const __half hh = __float2half_rn(vv);
        const size_t o = ((size_t)z * CD + d0 + ty + i * 8) * CS + s0 + tx;
        th[o] = hh;
        tl[o] = __float2half_rn(vv - __half2float(hh));
    }
}

// mem [H,D,D] -> memT [h, e, d] fp16 hi/lo
__global__ void memT_kernel(const float* __restrict__ mem,
                            __half* __restrict__ th, __half* __restrict__ tl)
{
    __shared__ float t[32][33];
    const int h = blockIdx.z;
    const int d0 = blockIdx.x * 32, e0 = blockIdx.y * 32;
    const int tx = threadIdx.x, ty = threadIdx.y;
#pragma unroll
    for (int i = 0; i < 4; i++)
        t[ty + i * 8][tx] = mem[(size_t)h * CD * CD + (size_t)(d0 + ty + i * 8) * CD + e0 + tx];
    __syncthreads();
#pragma unroll
    for (int i = 0; i < 4; i++) {
        const float v = t[tx][ty + i * 8];     // mem[d0+tx][e0+ty+i*8]
        const __half hh = __float2half_rn(v);
        const size_t o = (size_t)h * CD * CD + (size_t)(e0 + ty + i * 8) * CD + d0 + tx;
        th[o] = hh;
        tl[o] = __float2half_rn(v - __half2float(hh));
    }
}

// denq[bh][s] = sigma_q[row] . z_h ; denk likewise. One warp per row.
__global__ void denom_kernel(const float* __restrict__ sq, const float* __restrict__ sk,
                             const float* __restrict__ zv,
                             float* __restrict__ denq, float* __restrict__ denk)
{
    const int z = blockIdx.y;
    const int b = z / CH, h = z % CH;
    const int warp = threadIdx.x >> 5, lane = threadIdx.x & 31;
    const int s = blockIdx.x * 8 + warp;
    const size_t base = (size_t)(b * CS + s) * CE + (size_t)h * CD;
    const float* zp = zv + h * CD;
    float aq = 0.f, ak = 0.f;
#pragma unroll
    for (int d = lane; d < CD; d += 32) {
        const float zz = zp[d];
        aq = fmaf(sq[base + d], zz, aq);
        ak = fmaf(sk[base + d], zz, ak);
    }
#pragma unroll
    for (int o = 16; o > 0; o >>= 1) {
        aq += __shfl_xor_sync(0xffffffffu, aq, o);
        ak += __shfl_xor_sync(0xffffffffu, ak, o);
    }
    if (lane == 0) {
        denq[z * CS + s] = aq;
        denk[z * CS + s] = ak;
    }
}

// z_new partials: grid (CBH, 8); each chunk sums 256 rows
__global__ void znew_part_kernel(const float* __restrict__ sk, float* __restrict__ part)
{
    const int z = blockIdx.x, chunk = blockIdx.y;
    const int b = z / CH, h = z % CH;
    const int d = threadIdx.x;
    const float* p = sk + (size_t)(b * CS + chunk * 256) * CE + (size_t)h * CD + d;
    float sum = 0.f;
    for (int s = 0; s < 256; s += 8) {
        float t = 0.f;
#pragma unroll
        for (int u = 0; u < 8; u++) t += p[(size_t)(s + u) * CE];
        sum += t;
    }
    part[((size_t)z * 8 + chunk) * CD + d] = sum;
}

__global__ void znew_final_kernel(const float* __restrict__ part,
                                  const float* __restrict__ zv, float* __restrict__ outz)
{
    const int z = blockIdx.x;
    const int d = threadIdx.x;
    float sum = zv[(z % CH) * CD + d];
#pragma unroll
    for (int c = 0; c < 8; c++) sum += part[((size_t)z * 8 + c) * CD + d];
    outz[(size_t)z * CD + d] = sum;
}

// mem_new reduce: out = mem + sum of 4 split-K partials. grid CBH*64, 256 thr.
__global__ void memnew_reduce_kernel(const float* __restrict__ part,
                                     const float* __restrict__ mem, float* __restrict__ outm)
{
    const int z = blockIdx.x >> 6;               // bh
    const int blk = blockIdx.x & 63;
    const size_t e = (size_t)blk * 1024 + threadIdx.x * 4;
    const size_t bo = (size_t)z * CD * CD + e;
    float4 s = *(const float4*)(mem + (size_t)(z % CH) * CD * CD + e);
#pragma unroll
    for (int c = 0; c < 4; c++) {
        const float4 p = *(const float4*)(part + ((size_t)(z * 4 + c)) * CD * CD + e);
        s.x += p.x; s.y += p.y; s.z += p.z; s.w += p.w;
    }
    *(float4*)(outm + bo) = s;
}

// register-resident causal softmax: one warp per row, reads/writes only the
// causal prefix (rounded to 128-col tiles; PV's Keff clamp never reads beyond).
__global__ void __launch_bounds__(256)
softmax_reg_kernel(const float* __restrict__ P,
                   __half* __restrict__ oh, __half* __restrict__ ol)
{
    const int z = blockIdx.y;
    const int warp = threadIdx.x >> 5, lane = threadIdx.x & 31;
    const int row = blockIdx.x * 8 + warp;
    const size_t off = (size_t)z * CS * CS + (size_t)row * CS;
    const float4* p4 = (const float4*)(P + off);
    const int len = row + 1;
    const int ntiles = (row >> 7) + 1;   // 128-col tiles containing the prefix

    float v[64];
#pragma unroll
    for (int i = 0; i < 16; i++) {
        if (i < ntiles)
            *(float4*)(v + i * 4) = p4[i * 32 + lane];
        else {
            v[i * 4] = v[i * 4 + 1] = v[i * 4 + 2] = v[i * 4 + 3] = -3.0e38f;
        }
    }

    float m = -3.0e38f;
#pragma unroll
    for (int i = 0; i < 16; i++) {
        const int c = i * 128 + lane * 4;
#pragma unroll
        for (int j = 0; j < 4; j++) {
            if (c + j >= len) v[i * 4 + j] = -3.0e38f;
            m = fmaxf(m, v[i * 4 + j]);
        }
    }
#pragma unroll
    for (int o = 16; o > 0; o >>= 1) m = fmaxf(m, __shfl_xor_sync(0xffffffffu, m, o));

    float sum = 0.f;
#pragma unroll
    for (int i = 0; i < 64; i++) {
        v[i] = __expf(v[i] - m);       // masked -> exp(-huge) = 0
        sum += v[i];
    }
#pragma unroll
    for (int o = 16; o > 0; o >>= 1) sum += __shfl_xor_sync(0xffffffffu, sum, o);
    const float inv = 1.f / sum;

    __half* ph = oh + off;
    __half* pl = ol + off;
#pragma unroll
    for (int i = 0; i < 16; i++) {
        if (i >= ntiles) continue;     // PV never reads beyond the prefix tiles
        const int c = i * 128 + lane * 4;
        __half2 l0, l1;
        const __half2 h0 = split_hi2(v[i * 4] * inv, v[i * 4 + 1] * inv, l0);
        const __half2 h1 = split_hi2(v[i * 4 + 2] * inv, v[i * 4 + 3] * inv, l1);
        uint2 uh, ul;
        uh.x = *(const uint32_t*)&h0; uh.y = *(const uint32_t*)&h1;
        ul.x = *(const uint32_t*)&l0; ul.y = *(const uint32_t*)&l1;
        *(uint2*)(ph + c) = uh;
        *(uint2*)(pl + c) = ul;
    }
}

// ===========================================================================
extern "C" void kernel_launch(void* const* d_in, const int* in_sizes, int n_in,
                              void* d_out, int out_size)
{
    (void)in_sizes; (void)n_in; (void)out_size;
    const float* X     = (const float*)d_in[0];
    const float* Wq    = (const float*)d_in[1];
    const float* Wk    = (const float*)d_in[2];
    const float* Wv    = (const float*)d_in[3];
    const float* Wo    = (const float*)d_in[4];
    const float* bo    = (const float*)d_in[5];
    const float* betas = (const float*)d_in[6];
    const float* memp  = (const float*)d_in[7];
    const float* zp    = (const float*)d_in[8];
    float* out = (float*)d_out;

    float *pv, *psq, *psk, *pamem, *pU, *pP, *pdq, *pdk, *pzpart, *pmemp;
    cudaGetSymbolAddress((void**)&pv,    g_v);
    cudaGetSymbolAddress((void**)&psq,   g_sq);
    cudaGetSymbolAddress((void**)&psk,   g_sk);
    cudaGetSymbolAddress((void**)&pamem, g_amem);
    cudaGetSymbolAddress((void**)&pU,    g_U);
    cudaGetSymbolAddress((void**)&pP,    g_P);
    cudaGetSymbolAddress((void**)&pdq,   g_denq);
    cudaGetSymbolAddress((void**)&pdk,   g_denk);
    cudaGetSymbolAddress((void**)&pzpart, g_zpart);
    cudaGetSymbolAddress((void**)&pmemp, g_memp);

    __half *xh, *xl, *qh, *ql, *kh, *kl, *mh, *ml;
    __half *sqh, *sql, *skh, *skl;
    __half *wqh, *wql, *wkh, *wkl, *wvh, *wvl, *woh, *wol;
    __half *pph, *ppl, *vth, *vtl, *skth, *sktl, *uth, *utl, *mth, *mtl;
    cudaGetSymbolAddress((void**)&xh,   g_xh);   cudaGetSymbolAddress((void**)&xl,   g_xl);
    cudaGetSymbolAddress((void**)&qh,   g_qh);   cudaGetSymbolAddress((void**)&ql,   g_ql);
    cudaGetSymbolAddress((void**)&kh,   g_kh);   cudaGetSymbolAddress((void**)&kl,   g_kl);
    cudaGetSymbolAddress((void**)&mh,   g_mh);   cudaGetSymbolAddress((void**)&ml,   g_ml);
    cudaGetSymbolAddress((void**)&sqh,  g_sqh);  cudaGetSymbolAddress((void**)&sql,  g_sql);
    cudaGetSymbolAddress((void**)&skh,  g_skh);  cudaGetSymbolAddress((void**)&skl,  g_skl);
    cudaGetSymbolAddress((void**)&wqh,  g_wqh);  cudaGetSymbolAddress((void**)&wql,  g_wql);
    cudaGetSymbolAddress((void**)&wkh,  g_wkh);  cudaGetSymbolAddress((void**)&wkl,  g_wkl);
    cudaGetSymbolAddress((void**)&wvh,  g_wvh);  cudaGetSymbolAddress((void**)&wvl,  g_wvl);
    cudaGetSymbolAddress((void**)&woh,  g_woh);  cudaGetSymbolAddress((void**)&wol,  g_wol);
    cudaGetSymbolAddress((void**)&pph,  g_ph);   cudaGetSymbolAddress((void**)&ppl,  g_pl);
    cudaGetSymbolAddress((void**)&vth,  g_vth);  cudaGetSymbolAddress((void**)&vtl,  g_vtl);
    cudaGetSymbolAddress((void**)&skth, g_skth); cudaGetSymbolAddress((void**)&sktl, g_sktl);
    cudaGetSymbolAddress((void**)&uth,  g_uth);  cudaGetSymbolAddress((void**)&utl,  g_utl);
    cudaGetSymbolAddress((void**)&mth,  g_mth);  cudaGetSymbolAddress((void**)&mtl,  g_mtl);

    const int SM3 = 3 * 65536 + 1024;
    const int SM2 = 3 * 49152 + 1024;
    cudaFuncSetAttribute(hmma_gemm<9,3>,  cudaFuncAttributeMaxDynamicSharedMemorySize, SM3);
    cudaFuncSetAttribute(hmma_gemm<2,3>,  cudaFuncAttributeMaxDynamicSharedMemorySize, SM3);
    cudaFuncSetAttribute(hmma_gemm<10,3>, cudaFuncAttributeMaxDynamicSharedMemorySize, SM3);
    cudaFuncSetAttribute(hmma_gemm<0,2>,  cudaFuncAttributeMaxDynamicSharedMemorySize, SM2);
    cudaFuncSetAttribute(hmma_gemm<1,2>,  cudaFuncAttributeMaxDynamicSharedMemorySize, SM2);
    cudaFuncSetAttribute(hmma_gemm<3,2>,  cudaFuncAttributeMaxDynamicSharedMemorySize, SM2);
    cudaFuncSetAttribute(hmma_gemm<5,2>,  cudaFuncAttributeMaxDynamicSharedMemorySize, SM2);
    cudaFuncSetAttribute(hmma_gemm<6,2>,  cudaFuncAttributeMaxDynamicSharedMemorySize, SM2);

    const dim3 blkT(32, 8);
    const dim3 gSplitBig((unsigned)((size_t)CM * CE / 4 / 256));
    const dim3 gSplitW(CE / 32, CE / 32);
    const dim3 gProj(CE / 128, CM / 128, 1);     // 8 x 64
    const dim3 gQK(CS / 128, CS / 128, CBH);     // 16 x 16 x 16
    const dim3 gPV(CD / 128, CS / 128, CBH);     // 2 x 16 x 16
    const dim3 gAM(CD / 128, CS / 128, CBH);     // 2 x 16 x 16
    const dim3 gMU(CD / 128, CD / 128, CBH * 4); // 2 x 2 x 64 (split-K)
    const dim3 gTS(CS / 32, CD / 32, CBH);
    const dim3 gMT(CD / 32, CD / 32, CH);
    float* outmem = out + (size_t)CM * CE;
    float* outz   = outmem + (size_t)CBH * CD * CD;

    // 1) split inputs
    split_kernel<<<gSplitBig, 256>>>((const float4*)X, (uint2*)xh, (uint2*)xl);
    splitT_kernel<<<gSplitW, blkT>>>(Wq, wqh, wql);
    splitT_kernel<<<gSplitW, blkT>>>(Wk, wkh, wkl);
    splitT_kernel<<<gSplitW, blkT>>>(Wv, wvh, wvl);
    splitT_kernel<<<gSplitW, blkT>>>(Wo, woh, wol);
    memT_kernel<<<gMT, blkT>>>(memp, mth, mtl);

    // 2) projections: Q/K 3-term with fused sigma (split q + f32 sigma + split sigma);
    //    V 2-term f32 out
    hmma_gemm<9,3><<<gProj, 256, SM3>>>(xh, xl, wqh, wql, psq, qh, ql, sqh, sql, CE, CE, CE, CE, nullptr, nullptr);
    hmma_gemm<9,3><<<gProj, 256, SM3>>>(xh, xl, wkh, wkl, psk, kh, kl, skh, skl, CE, CE, CE, CE, nullptr, nullptr);
    hmma_gemm<0,2><<<gProj, 256, SM2>>>(xh, xl, wvh, wvl, pv, nullptr, nullptr, nullptr, nullptr, CE, CE, CE, CE, nullptr, nullptr);

    // 3) denominators + z_new
    denom_kernel<<<dim3(CS / 8, CBH), 256>>>(psq, psk, zp, pdq, pdk);
    znew_part_kernel<<<dim3(CBH, 8), CD>>>(psk, pzpart);
    znew_final_kernel<<<CBH, CD>>>(pzpart, zp, outz);

    // 4) compressive-memory read: A_mem = (sq @ mem)/(sq.z+1e-6)  [2-term]
    hmma_gemm<5,2><<<gAM, 256, SM2>>>(sqh, sql, mth, mtl, pamem, nullptr, nullptr, nullptr, nullptr, CD, CE, CD, CE, pdq, nullptr);

    // 5) causal softmax attention (QK 3-term; PV 2-term with gate-mix + split out)
    hmma_gemm<2,3><<<gQK, 256, SM3>>>(qh, ql, kh, kl, pP, nullptr, nullptr, nullptr, nullptr, CD, CE, CE, CS, nullptr, nullptr);
    softmax_reg_kernel<<<dim3(CS / 8, CBH), 256>>>(pP, pph, ppl);
    tsplit_head_kernel<<<gTS, blkT>>>(pv, vth, vtl);
    hmma_gemm<3,2><<<gPV, 256, SM2>>>(pph, ppl, vth, vtl, nullptr, mh, ml, nullptr, nullptr, CS, CS, CS, CE, pamem, betas);

    // 6) memory update: U [2-term]; mem_new via split-K [3-term] + reduce
    hmma_gemm<6,2><<<gAM, 256, SM2>>>(skh, skl, mth, mtl, pU, nullptr, nullptr, nullptr, nullptr, CD, CE, CD, CE, pdk, pv);
    tsplit_head_kernel<<<gTS, blkT>>>(psk, skth, sktl);
    tsplit_head_kernel<<<gTS, blkT>>>(pU, uth, utl);
    hmma_gemm<10,3><<<gMU, 256, SM3>>>(skth, sktl, uth, utl, pmemp, nullptr, nullptr, nullptr, nullptr, 512, CS, CS, CD, nullptr, nullptr);
    memnew_reduce_kernel<<<CBH * 64, 256>>>(pmemp, memp, outmem);

    // 7) output projection + bias [2-term]
    hmma_gemm<1,2><<<gProj, 256, SM2>>>(mh, ml, woh, wol, out, nullptr, nullptr, nullptr, nullptr, CE, CE, CE, CE, bo, nullptr);
}

// round 14
// speedup vs baseline: 1.0407x; 1.0407x over previous
#include <cuda_runtime.h>
#include <cuda_fp16.h>
#include <cstdint>
#include <math.h>

// Problem constants
#define CB 4
#define CS 2048
#define CE 1024
#define CH 4
#define CD 256
#define CBH 16      // B*H
#define CM 8192     // B*S tokens

// ---------------- f32 scratch ----------------
__device__ float g_v   [(size_t)CM * CE];
__device__ float g_sq  [(size_t)CM * CE];
__device__ float g_sk  [(size_t)CM * CE];
__device__ float g_amem[(size_t)CM * CE];
__device__ float g_U   [(size_t)CM * CE];
__device__ float g_P   [(size_t)CBH * CS * CS];   // f32 logits
__device__ float g_denq[CBH * CS];
__device__ float g_denk[CBH * CS];
__device__ float g_zpart[CBH * 8 * CD];
__device__ float g_memp[(size_t)4 * CBH * CD * CD];  // split-K partials

// ---------------- fp16 scratch (uint4-typed for 16B alignment) ----------------
__device__ uint4 g_xh  [(size_t)CM * CE / 8];
__device__ uint4 g_xl  [(size_t)CM * CE / 8];
__device__ uint4 g_qh  [(size_t)CM * CE / 8];
__device__ uint4 g_ql  [(size_t)CM * CE / 8];
__device__ uint4 g_kh  [(size_t)CM * CE / 8];
__device__ uint4 g_kl  [(size_t)CM * CE / 8];
__device__ uint4 g_mh  [(size_t)CM * CE / 8];   // PV mix split
__device__ uint4 g_ml  [(size_t)CM * CE / 8];
__device__ uint4 g_sqh [(size_t)CM * CE / 8];
__device__ uint4 g_sql [(size_t)CM * CE / 8];
__device__ uint4 g_skh [(size_t)CM * CE / 8];
__device__ uint4 g_skl [(size_t)CM * CE / 8];
__device__ uint4 g_wqh [(size_t)CE * CE / 8];
__device__ uint4 g_wql [(size_t)CE * CE / 8];
__device__ uint4 g_wkh [(size_t)CE * CE / 8];
__device__ uint4 g_wkl [(size_t)CE * CE / 8];
__device__ uint4 g_wvh [(size_t)CE * CE / 8];
__device__ uint4 g_wvl [(size_t)CE * CE / 8];
__device__ uint4 g_woh [(size_t)CE * CE / 8];
__device__ uint4 g_wol [(size_t)CE * CE / 8];
__device__ uint4 g_ph  [(size_t)CBH * CS * CS / 8];  // softmax probs hi
__device__ uint4 g_pl  [(size_t)CBH * CS * CS / 8];  // softmax probs lo
__device__ uint4 g_vth [(size_t)CBH * CD * CS / 8];  // v^T per head
__device__ uint4 g_vtl [(size_t)CBH * CD * CS / 8];
__device__ uint4 g_skth[(size_t)CBH * CD * CS / 8];  // sk^T per head
__device__ uint4 g_sktl[(size_t)CBH * CD * CS / 8];
__device__ uint4 g_uth [(size_t)CBH * CD * CS / 8];  // U^T per head
__device__ uint4 g_utl [(size_t)CBH * CD * CS / 8];
__device__ uint4 g_mth [(size_t)CH * CD * CD / 8];   // mem^T per head
__device__ uint4 g_mtl [(size_t)CH * CD * CD / 8];

// ======================= helpers =======================
__device__ __forceinline__ uint32_t smem_u32(const void* p) {
    uint32_t a;
    asm("{ .reg .u64 t; cvta.to.shared.u64 t, %1; cvt.u32.u64 %0, t; }" : "=r"(a) : "l"(p));
    return a;
}
#define CPA16(dst, src) \
    asm volatile("cp.async.cg.shared.global [%0], [%1], 16;" :: "r"(dst), "l"(src))
#define CP_COMMIT() asm volatile("cp.async.commit_group;")
#define CP_WAIT2()  asm volatile("cp.async.wait_group 2;")

#define LDSM4(r, addr) \
    asm volatile("ldmatrix.sync.aligned.m8n8.x4.shared.b16 {%0,%1,%2,%3}, [%4];" \
        : "=r"((r)[0]), "=r"((r)[1]), "=r"((r)[2]), "=r"((r)[3]) : "r"(addr))

#define MMA16816(d, a, b0, b1) \
    asm volatile("mma.sync.aligned.m16n8k16.row.col.f32.f16.f16.f32 " \
        "{%0,%1,%2,%3}, {%4,%5,%6,%7}, {%8,%9}, {%0,%1,%2,%3};" \
        : "+f"((d)[0]), "+f"((d)[1]), "+f"((d)[2]), "+f"((d)[3]) \
        : "r"((a)[0]), "r"((a)[1]), "r"((a)[2]), "r"((a)[3]), "r"(b0), "r"(b1))

__device__ __forceinline__ __half2 split_hi2(float a, float b, __half2& lo) {
    const __half h0 = __float2half_rn(a), h1 = __float2half_rn(b);
    lo = __halves2half2(__float2half_rn(a - __half2float(h0)),
                        __float2half_rn(b - __half2float(h1)));
    return __halves2half2(h0, h1);
}

// ===========================================================================
// HMMA split-fp16 GEMM: C[M,N] = A·B^T. A:[rows,K] K-major lda, B:[cols,K] ldb.
// NTERM=3: Ah·Bh + Ah·Bl + Al·Bh. NTERM=2: Ah·Bh + Al·Bh (B hi-only).
// Tile 128x128, KT=64, 3-stage cp.async. 8 warps (4M x 2N). R5-proven config.
// EPI: 0 f32 | 1 f32+bias | 2 QK causal (skip masked, z=bh) | 3 PV gate-mix ->
//      split out | 4 split out (Q/K proj) | 5 A_mem acc/den | 6 U=v-acc/den |
//      10 split-K partial f32 (mem update)
// ===========================================================================
template <int EPI, int NTERM>
__global__ void __launch_bounds__(256, 1)
hmma_gemm(const __half* __restrict__ Ah, const __half* __restrict__ Al,
          const __half* __restrict__ Bh, const __half* __restrict__ Bl,
          float* __restrict__ Cg, __half* __restrict__ Oh, __half* __restrict__ Ol,
          int K, int lda, int ldb, int ldc,
          const float* __restrict__ aux0, const float* __restrict__ aux1)
{
    const int m0 = blockIdx.y * 128, n0 = blockIdx.x * 128;
    const int z = blockIdx.z;
    constexpr int SS = (NTERM == 3) ? 65536 : 49152;   // stage stride
    size_t offA = 0, offB = 0, offC = 0;
    const float* amem = nullptr;
    const float* den  = nullptr;
    const float* vsrc = nullptr;
    float gate = 0.f, omg = 0.f;
    int Keff = K;
    if (EPI == 2) {
        if (n0 >= m0 + 128) return;   // fully masked tile: softmax never reads it
        const int b = z / CH, h = z % CH;
        offA = offB = (size_t)b * CS * CE + (size_t)h * CD;
        offC = (size_t)z * CS * CS;
    } else if (EPI == 3) {
        const int b = z / CH, h = z % CH;
        offA = (size_t)z * CS * CS;
        offB = (size_t)z * CD * CS;
        offC = (size_t)b * CS * CE + (size_t)h * CD;
        amem = aux0 + offC;
        gate = 1.f / (1.f + __expf(-aux1[h]));
        omg  = 1.f - gate;
        Keff = min(K, m0 + 128);      // probs zero beyond row block
    } else if (EPI == 5 || EPI == 6) {
        const int b = z / CH, h = z % CH;
        offA = (size_t)b * CS * CE + (size_t)h * CD;
        offB = (size_t)h * CD * CD;
        offC = offA;
        den  = aux0 + (size_t)z * CS;
        if (EPI == 6) vsrc = aux1 + offC;
    } else if (EPI == 10) {
        // split-K mem-update partial: z = bh*4 + chunk, K = 512 per chunk
        const int bh = z >> 2, chunk = z & 3;
        offA = (size_t)bh * CD * CS + (size_t)chunk * 512;
        offB = offA;
        offC = (size_t)z * CD * CD;
    }

    extern __shared__ char dsm_raw[];
    char* base = dsm_raw + ((1024 - (smem_u32(dsm_raw) & 1023)) & 1023);
    const uint32_t sb = smem_u32(base);

    const int tid = threadIdx.x;
    const int wid = tid >> 5, lane = tid & 31;
    const int wm = wid & 3, wn = wid >> 2;

    const __half* pAh = Ah + offA;
    const __half* pAl = Al + offA;
    const __half* pBh = Bh + offB;
    const __half* pBl = Bl + offB;

    auto load_stage = [&](int kt, int stage) {
        const int k0 = kt * 64;
        const uint32_t sbase = sb + stage * SS;
        constexpr int NIT = (NTERM == 3) ? 16 : 12;
#pragma unroll
        for (int it = 0; it < NIT; it++) {
            const int mat = it >> 2;
            const int rem = tid + (it & 3) * 256;
            const int row = rem >> 3, k8 = rem & 7;
            const uint32_t dst = sbase + mat * 16384 + row * 128 + ((k8 ^ (row & 7)) << 4);
            const __half* src;
            if (mat == 0)      src = pAh + (size_t)(m0 + row) * lda + k0 + k8 * 8;
            else if (mat == 1) src = pAl + (size_t)(m0 + row) * lda + k0 + k8 * 8;
            else if (mat == 2) src = pBh + (size_t)(n0 + row) * ldb + k0 + k8 * 8;
            else               src = pBl + (size_t)(n0 + row) * ldb + k0 + k8 * 8;
            CPA16(dst, src);
        }
    };

    float acc[2][8][4];
#pragma unroll
    for (int mi = 0; mi < 2; mi++)
#pragma unroll
        for (int nj = 0; nj < 8; nj++)
#pragma unroll
            for (int r = 0; r < 4; r++) acc[mi][nj][r] = 0.f;

    const int nkt = Keff / 64;   // >= 2 everywhere

    load_stage(0, 0); CP_COMMIT();
    load_stage(1, 1); CP_COMMIT();
    load_stage(2, 2); CP_COMMIT();   // may prefetch past Keff: in-bounds, unused

    int buf = 0;
    for (int kt = 0; kt < nkt; kt++) {
        CP_WAIT2();
        __syncthreads();
        const uint32_t sA = sb + buf * SS;
        const uint32_t sB = sA + 32768;
#pragma unroll
        for (int ks = 0; ks < 4; ks++) {
            uint32_t af[2][2][4];
#pragma unroll
            for (int mi = 0; mi < 2; mi++) {
                const int row = wm * 32 + mi * 16 + (lane & 15);
                const int k8 = ks * 2 + (lane >> 4);
                const uint32_t off = row * 128 + ((k8 ^ (row & 7)) << 4);
                LDSM4(af[mi][0], sA + off);
                LDSM4(af[mi][1], sA + 16384 + off);
            }
            uint32_t bf[4][2][4];
#pragma unroll
            for (int np = 0; np < 4; np++) {
                const int n = wn * 64 + np * 16 + (lane & 7) + ((lane >> 4) << 3);
                const int k8 = ks * 2 + ((lane >> 3) & 1);
                const uint32_t off = n * 128 + ((k8 ^ (n & 7)) << 4);
                LDSM4(bf[np][0], sB + off);
                if (NTERM == 3) LDSM4(bf[np][1], sB + 16384 + off);
            }
#pragma unroll
            for (int mi = 0; mi < 2; mi++)
#pragma unroll
                for (int nj = 0; nj < 8; nj++) {
                    const uint32_t* bh = &bf[nj >> 1][0][(nj & 1) * 2];
                    MMA16816(acc[mi][nj], af[mi][0], bh[0], bh[1]);
                    if (NTERM == 3) {
                        const uint32_t* bl = &bf[nj >> 1][1][(nj & 1) * 2];
                        MMA16816(acc[mi][nj], af[mi][0], bl[0], bl[1]);
                    }
                    MMA16816(acc[mi][nj], af[mi][1], bh[0], bh[1]);
                }
        }
        __syncthreads();
        if (kt + 3 < nkt) load_stage(kt + 3, buf);
        CP_COMMIT();
        buf = (buf == 2) ? 0 : buf + 1;
    }

    // ---- epilogue ----
#pragma unroll
    for (int mi = 0; mi < 2; mi++) {
#pragma unroll
        for (int nj = 0; nj < 8; nj++) {
            const int gr0 = m0 + wm * 32 + mi * 16 + (lane >> 2);
            const int gc  = n0 + wn * 64 + nj * 8 + (lane & 3) * 2;
#pragma unroll
            for (int hf = 0; hf < 2; hf++) {
                const int gr = gr0 + hf * 8;
                const size_t idx = (size_t)gr * ldc + gc;
                float d0 = acc[mi][nj][hf * 2], d1 = acc[mi][nj][hf * 2 + 1];
                if (EPI == 1) { d0 += aux0[gc]; d1 += aux0[gc + 1]; }
                if (EPI == 3) {
                    d0 = gate * amem[idx] + omg * d0;
                    d1 = gate * amem[idx + 1] + omg * d1;
                }
                if (EPI == 5) {
                    const float r = 1.f / (den[gr] + 1e-6f);
                    d0 *= r; d1 *= r;
                }
                if (EPI == 6) {
                    const float r = 1.f / (den[gr] + 1e-6f);
                    d0 = vsrc[idx] - d0 * r;
                    d1 = vsrc[idx + 1] - d1 * r;
                }
                if (EPI == 3 || EPI == 4) {
                    __half2 lo;
                    const __half2 hi = split_hi2(d0, d1, lo);
                    *(__half2*)(Oh + offC + idx) = hi;
                    *(__half2*)(Ol + offC + idx) = lo;
                } else {
                    *(float2*)(Cg + offC + idx) = make_float2(d0, d1);
                }
            }
        }
    }
}

// ===========================================================================
// split / transpose-split kernels
// ===========================================================================
__global__ void split_kernel(const float4* __restrict__ in,
                             uint2* __restrict__ hi, uint2* __restrict__ lo)
{
    const size_t i = (size_t)blockIdx.x * blockDim.x + threadIdx.x;
    const float4 v = in[i];
    __half2 l0, l1;
    const __half2 h0 = split_hi2(v.x, v.y, l0);
    const __half2 h1 = split_hi2(v.z, v.w, l1);
    uint2 uh, ul;
    uh.x = *(const uint32_t*)&h0; uh.y = *(const uint32_t*)&h1;
    ul.x = *(const uint32_t*)&l0; ul.y = *(const uint32_t*)&l1;
    hi[i] = uh; lo[i] = ul;
}

// W[K,N] (1024x1024) -> Wt_hi/lo[N,K]
__global__ void splitT_kernel(const float* __restrict__ W,
                              __half* __restrict__ th, __half* __restrict__ tl)
{
    __shared__ float t[32][33];
    const int n0 = blockIdx.x * 32, k0 = blockIdx.y * 32;
    const int tx = threadIdx.x, ty = threadIdx.y;
#pragma unroll
    for (int i = 0; i < 4; i++)
        t[ty + i * 8][tx] = W[(size_t)(k0 + ty + i * 8) * CE + n0 + tx];
    __syncthreads();
#pragma unroll
    for (int i = 0; i < 4; i++) {
        const float v = t[tx][ty + i * 8];
        const __half h = __float2half_rn(v);
        const size_t o = (size_t)(n0 + ty + i * 8) * CE + k0 + tx;
        th[o] = h;
        tl[o] = __float2half_rn(v - __half2float(h));
    }
}

// src [B,S,E] head slice -> dst [bh, D, S] fp16 hi/lo (transpose + split)
__global__ void tsplit_head_kernel(const float* __restrict__ src,
                                   __half* __restrict__ th, __half* __restrict__ tl)
{
    __shared__ float t[32][33];
    const int z = blockIdx.z, b = z / CH, h = z % CH;
    const int s0 = blockIdx.x * 32, d0 = blockIdx.y * 32;
    const int tx = threadIdx.x, ty = threadIdx.y;
#pragma unroll
    for (int i = 0; i < 4; i++)
        t[ty + i * 8][tx] = src[(size_t)(b * CS + s0 + ty + i * 8) * CE + h * CD + d0 + tx];
    __syncthreads();
#pragma unroll
    for (int i = 0; i < 4; i++) {
        const float vv = t[tx][ty + i * 8];
        const __half hh = __float2half_rn(vv);
        const size_t o = ((size_t)z * CD + d0 + ty + i * 8) * CS + s0 + tx;
        th[o] = hh;
        tl[o] = __float2half_rn(vv - __half2float(hh));
    }
}

// mem [H,D,D] -> memT [h, e, d] fp16 hi/lo
__global__ void memT_kernel(const float* __restrict__ mem,
                            __half* __restrict__ th, __half* __restrict__ tl)
{
    __shared__ float t[32][33];
    const int h = blockIdx.z;
    const int d0 = blockIdx.x * 32, e0 = blockIdx.y * 32;
    const int tx = threadIdx.x, ty = threadIdx.y;
#pragma unroll
    for (int i = 0; i < 4; i++)
        t[ty + i * 8][tx] = mem[(size_t)h * CD * CD + (size_t)(d0 + ty + i * 8) * CD + e0 + tx];
    __syncthreads();
#pragma unroll
    for (int i = 0; i < 4; i++) {
        const float v = t[tx][ty + i * 8];     // mem[d0+tx][e0+ty+i*8]
        const __half hh = __float2half_rn(v);
        const size_t o = (size_t)h * CD * CD + (size_t)(e0 + ty + i * 8) * CD + d0 + tx;
        th[o] = hh;
        tl[o] = __float2half_rn(v - __half2float(hh));
    }
}

// sigma from split q/k: s = elu(hi+lo)+1; writes f32 + split fp16
__global__ void sigma2_kernel(const uint2* __restrict__ qh, const uint2* __restrict__ ql,
                              const uint2* __restrict__ kh, const uint2* __restrict__ kl,
                              float4* __restrict__ sqf, float4* __restrict__ skf,
                              uint2* __restrict__ sqh, uint2* __restrict__ sql,
                              uint2* __restrict__ skh, uint2* __restrict__ skl)
{
    const size_t i = (size_t)blockIdx.x * blockDim.x + threadIdx.x;
    auto recon = [](uint2 h, uint2 l, float* o) {
        const __half2 h0 = *(__half2*)&h.x, h1 = *(__half2*)&h.y;
        const __half2 l0 = *(__half2*)&l.x, l1 = *(__half2*)&l.y;
        o[0] = __half2float(h0.x) + __half2float(l0.x);
        o[1] = __half2float(h0.y) + __half2float(l0.y);
        o[2] = __half2float(h1.x) + __half2float(l1.x);
        o[3] = __half2float(h1.y) + __half2float(l1.y);
    };
    auto elu1 = [](float x) { return (x > 0.f) ? x + 1.f : __expf(x); };

    float x[4];
    recon(qh[i], ql[i], x);
#pragma unroll
    for (int j = 0; j < 4; j++) x[j] = elu1(x[j]);
    sqf[i] = make_float4(x[0], x[1], x[2], x[3]);
    {
        __half2 l0, l1;
        const __half2 h0 = split_hi2(x[0], x[1], l0);
        const __half2 h1 = split_hi2(x[2], x[3], l1);
        uint2 uh, ul;
        uh.x = *(const uint32_t*)&h0; uh.y = *(const uint32_t*)&h1;
        ul.x = *(const uint32_t*)&l0; ul.y = *(const uint32_t*)&l1;
        sqh[i] = uh; sql[i] = ul;
    }
    recon(kh[i], kl[i], x);
#pragma unroll
    for (int j = 0; j < 4; j++) x[j] = elu1(x[j]);
    skf[i] = make_float4(x[0], x[1], x[2], x[3]);
    {
        __half2 l0, l1;
        const __half2 h0 = split_hi2(x[0], x[1], l0);
        const __half2 h1 = split_hi2(x[2], x[3], l1);
        uint2 uh, ul;
        uh.x = *(const uint32_t*)&h0; uh.y = *(const uint32_t*)&h1;
        ul.x = *(const uint32_t*)&l0; ul.y = *(const uint32_t*)&l1;
        skh[i] = uh; skl[i] = ul;
    }
}

// denq[bh][s] = sigma_q[row] . z_h ; denk likewise. One warp per row.
__global__ void denom_kernel(const float* __restrict__ sq, const float* __restrict__ sk,
                             const float* __restrict__ zv,
                             float* __restrict__ denq, float* __restrict__ denk)
{
    const int z = blockIdx.y;
    const int b = z / CH, h = z % CH;
    const int warp = threadIdx.x >> 5, lane = threadIdx.x & 31;
    const int s = blockIdx.x * 8 + warp;
    const size_t base = (size_t)(b * CS + s) * CE + (size_t)h * CD;
    const float* zp = zv + h * CD;
    float aq = 0.f, ak = 0.f;
#pragma unroll
    for (int d = lane; d < CD; d += 32) {
        const float zz = zp[d];
        aq = fmaf(sq[base + d], zz, aq);
        ak = fmaf(sk[base + d], zz, ak);
    }
#pragma unroll
    for (int o = 16; o > 0; o >>= 1) {
        aq += __shfl_xor_sync(0xffffffffu, aq, o);
        ak += __shfl_xor_sync(0xffffffffu, ak, o);
    }
    if (lane == 0) {
        denq[z * CS + s] = aq;
        denk[z * CS + s] = ak;
    }
}

// z_new partials: grid (CBH, 8); each chunk sums 256 rows
__global__ void znew_part_kernel(const float* __restrict__ sk, float* __restrict__ part)
{
    const int z = blockIdx.x, chunk = blockIdx.y;
    const int b = z / CH, h = z % CH;
    const int d = threadIdx.x;
    const float* p = sk + (size_t)(b * CS + chunk * 256) * CE + (size_t)h * CD + d;
    float sum = 0.f;
    for (int s = 0; s < 256; s += 8) {
        float t = 0.f;
#pragma unroll
        for (int u = 0; u < 8; u++) t += p[(size_t)(s + u) * CE];
        sum += t;
    }
    part[((size_t)z * 8 + chunk) * CD + d] = sum;
}

__global__ void znew_final_kernel(const float* __restrict__ part,
                                  const float* __restrict__ zv, float* __restrict__ outz)
{
    const int z = blockIdx.x;
    const int d = threadIdx.x;
    float sum = zv[(z % CH) * CD + d];
#pragma unroll
    for (int c = 0; c < 8; c++) sum += part[((size_t)z * 8 + c) * CD + d];
    outz[(size_t)z * CD + d] = sum;
}

// mem_new reduce: out = mem + sum of 4 split-K partials. grid CBH*64, 256 thr.
__global__ void memnew_reduce_kernel(const float* __restrict__ part,
                                     const float* __restrict__ mem, float* __restrict__ outm)
{
    const int z = blockIdx.x >> 6;               // bh
    const int blk = blockIdx.x & 63;
    const size_t e = (size_t)blk * 1024 + threadIdx.x * 4;
    const size_t bo = (size_t)z * CD * CD + e;
    float4 s = *(const float4*)(mem + (size_t)(z % CH) * CD * CD + e);
#pragma unroll
    for (int c = 0; c < 4; c++) {
        const float4 p = *(const float4*)(part + ((size_t)(z * 4 + c)) * CD * CD + e);
        s.x += p.x; s.y += p.y; s.z += p.z; s.w += p.w;
    }
    *(float4*)(outm + bo) = s;
}

// register-resident causal softmax: one warp per row, reads/writes only the
// causal prefix (rounded to 128-col tiles; PV's Keff clamp never reads beyond).
__global__ void __launch_bounds__(256)
softmax_reg_kernel(const float* __restrict__ P,
                   __half* __restrict__ oh, __half* __restrict__ ol)
{
    const int z = blockIdx.y;
    const int warp = threadIdx.x >> 5, lane = threadIdx.x & 31;
    const int row = blockIdx.x * 8 + warp;
    const size_t off = (size_t)z * CS * CS + (size_t)row * CS;
    const float4* p4 = (const float4*)(P + off);
    const int len = row + 1;
    const int ntiles = (row >> 7) + 1;   // 128-col tiles containing the prefix

    float v[64];
#pragma unroll
    for (int i = 0; i < 16; i++) {
        if (i < ntiles)
            *(float4*)(v + i * 4) = p4[i * 32 + lane];
        else {
            v[i * 4] = v[i * 4 + 1] = v[i * 4 + 2] = v[i * 4 + 3] = -3.0e38f;
        }
    }

    float m = -3.0e38f;
#pragma unroll
    for (int i = 0; i < 16; i++) {
        const int c = i * 128 + lane * 4;
#pragma unroll
        for (int j = 0; j < 4; j++) {
            if (c + j >= len) v[i * 4 + j] = -3.0e38f;
            m = fmaxf(m, v[i * 4 + j]);
        }
    }
#pragma unroll
    for (int o = 16; o > 0; o >>= 1) m = fmaxf(m, __shfl_xor_sync(0xffffffffu, m, o));

    float sum = 0.f;
#pragma unroll
    for (int i = 0; i < 64; i++) {
        v[i] = __expf(v[i] - m);       // masked -> exp(-huge) = 0
        sum += v[i];
    }
#pragma unroll
    for (int o = 16; o > 0; o >>= 1) sum += __shfl_xor_sync(0xffffffffu, sum, o);
    const float inv = 1.f / sum;

    __half* ph = oh + off;
    __half* pl = ol + off;
#pragma unroll
    for (int i = 0; i < 16; i++) {
        if (i >= ntiles) continue;     // PV never reads beyond the prefix tiles
        const int c = i * 128 + lane * 4;
        __half2 l0, l1;
        const __half2 h0 = split_hi2(v[i * 4] * inv, v[i * 4 + 1] * inv, l0);
        const __half2 h1 = split_hi2(v[i * 4 + 2] * inv, v[i * 4 + 3] * inv, l1);
        uint2 uh, ul;
        uh.x = *(const uint32_t*)&h0; uh.y = *(const uint32_t*)&h1;
        ul.x = *(const uint32_t*)&l0; ul.y = *(const uint32_t*)&l1;
        *(uint2*)(ph + c) = uh;
        *(uint2*)(pl + c) = ul;
    }
}

// ===========================================================================
extern "C" void kernel_launch(void* const* d_in, const int* in_sizes, int n_in,
                              void* d_out, int out_size)
{
    (void)in_sizes; (void)n_in; (void)out_size;
    const float* X     = (const float*)d_in[0];
    const float* Wq    = (const float*)d_in[1];
    const float* Wk    = (const float*)d_in[2];
    const float* Wv    = (const float*)d_in[3];
    const float* Wo    = (const float*)d_in[4];
    const float* bo    = (const float*)d_in[5];
    const float* betas = (const float*)d_in[6];
    const float* memp  = (const float*)d_in[7];
    const float* zp    = (const float*)d_in[8];
    float* out = (float*)d_out;

    float *pv, *psq, *psk, *pamem, *pU, *pP, *pdq, *pdk, *pzpart, *pmemp;
    cudaGetSymbolAddress((void**)&pv,    g_v);
    cudaGetSymbolAddress((void**)&psq,   g_sq);
    cudaGetSymbolAddress((void**)&psk,   g_sk);
    cudaGetSymbolAddress((void**)&pamem, g_amem);
    cudaGetSymbolAddress((void**)&pU,    g_U);
    cudaGetSymbolAddress((void**)&pP,    g_P);
    cudaGetSymbolAddress((void**)&pdq,   g_denq);
    cudaGetSymbolAddress((void**)&pdk,   g_denk);
    cudaGetSymbolAddress((void**)&pzpart, g_zpart);
    cudaGetSymbolAddress((void**)&pmemp, g_memp);

    __half *xh, *xl, *qh, *ql, *kh, *kl, *mh, *ml;
    __half *sqh, *sql, *skh, *skl;
    __half *wqh, *wql, *wkh, *wkl, *wvh, *wvl, *woh, *wol;
    __half *pph, *ppl, *vth, *vtl, *skth, *sktl, *uth, *utl, *mth, *mtl;
    cudaGetSymbolAddress((void**)&xh,   g_xh);   cudaGetSymbolAddress((void**)&xl,   g_xl);
    cudaGetSymbolAddress((void**)&qh,   g_qh);   cudaGetSymbolAddress((void**)&ql,   g_ql);
    cudaGetSymbolAddress((void**)&kh,   g_kh);   cudaGetSymbolAddress((void**)&kl,   g_kl);
    cudaGetSymbolAddress((void**)&mh,   g_mh);   cudaGetSymbolAddress((void**)&ml,   g_ml);
    cudaGetSymbolAddress((void**)&sqh,  g_sqh);  cudaGetSymbolAddress((void**)&sql,  g_sql);
    cudaGetSymbolAddress((void**)&skh,  g_skh);  cudaGetSymbolAddress((void**)&skl,  g_skl);
    cudaGetSymbolAddress((void**)&wqh,  g_wqh);  cudaGetSymbolAddress((void**)&wql,  g_wql);
    cudaGetSymbolAddress((void**)&wkh,  g_wkh);  cudaGetSymbolAddress((void**)&wkl,  g_wkl);
    cudaGetSymbolAddress((void**)&wvh,  g_wvh);  cudaGetSymbolAddress((void**)&wvl,  g_wvl);
    cudaGetSymbolAddress((void**)&woh,  g_woh);  cudaGetSymbolAddress((void**)&wol,  g_wol);
    cudaGetSymbolAddress((void**)&pph,  g_ph);   cudaGetSymbolAddress((void**)&ppl,  g_pl);
    cudaGetSymbolAddress((void**)&vth,  g_vth);  cudaGetSymbolAddress((void**)&vtl,  g_vtl);
    cudaGetSymbolAddress((void**)&skth, g_skth); cudaGetSymbolAddress((void**)&sktl, g_sktl);
    cudaGetSymbolAddress((void**)&uth,  g_uth);  cudaGetSymbolAddress((void**)&utl,  g_utl);
    cudaGetSymbolAddress((void**)&mth,  g_mth);  cudaGetSymbolAddress((void**)&mtl,  g_mtl);

    const int SM3 = 3 * 65536 + 1024;
    const int SM2 = 3 * 49152 + 1024;
    cudaFuncSetAttribute(hmma_gemm<4,3>,  cudaFuncAttributeMaxDynamicSharedMemorySize, SM3);
    cudaFuncSetAttribute(hmma_gemm<2,3>,  cudaFuncAttributeMaxDynamicSharedMemorySize, SM3);
    cudaFuncSetAttribute(hmma_gemm<10,3>, cudaFuncAttributeMaxDynamicSharedMemorySize, SM3);
    cudaFuncSetAttribute(hmma_gemm<0,2>,  cudaFuncAttributeMaxDynamicSharedMemorySize, SM2);
    cudaFuncSetAttribute(hmma_gemm<1,2>,  cudaFuncAttributeMaxDynamicSharedMemorySize, SM2);
    cudaFuncSetAttribute(hmma_gemm<3,2>,  cudaFuncAttributeMaxDynamicSharedMemorySize, SM2);
    cudaFuncSetAttribute(hmma_gemm<5,2>,  cudaFuncAttributeMaxDynamicSharedMemorySize, SM2);
    cudaFuncSetAttribute(hmma_gemm<6,2>,  cudaFuncAttributeMaxDynamicSharedMemorySize, SM2);

    const dim3 blkT(32, 8);
    const dim3 gSplitBig((unsigned)((size_t)CM * CE / 4 / 256));
    const dim3 gSplitW(CE / 32, CE / 32);
    const dim3 gProj(CE / 128, CM / 128, 1);     // 8 x 64
    const dim3 gQK(CS / 128, CS / 128, CBH);     // 16 x 16 x 16
    const dim3 gPV(CD / 128, CS / 128, CBH);     // 2 x 16 x 16
    const dim3 gAM(CD / 128, CS / 128, CBH);     // 2 x 16 x 16
    const dim3 gMU(CD / 128, CD / 128, CBH * 4); // 2 x 2 x 64 (split-K)
    const dim3 gTS(CS / 32, CD / 32, CBH);
    const dim3 gMT(CD / 32, CD / 32, CH);
    float* outmem = out + (size_t)CM * CE;
    float* outz   = outmem + (size_t)CBH * CD * CD;

    // 1) split inputs
    split_kernel<<<gSplitBig, 256>>>((const float4*)X, (uint2*)xh, (uint2*)xl);
    splitT_kernel<<<gSplitW, blkT>>>(Wq, wqh, wql);
    splitT_kernel<<<gSplitW, blkT>>>(Wk, wkh, wkl);
    splitT_kernel<<<gSplitW, blkT>>>(Wv, wvh, wvl);
    splitT_kernel<<<gSplitW, blkT>>>(Wo, woh, wol);
    memT_kernel<<<gMT, blkT>>>(memp, mth, mtl);

    // 2) projections (Q/K 3-term, split out; V 2-term f32 out)
    hmma_gemm<4,3><<<gProj, 256, SM3>>>(xh, xl, wqh, wql, nullptr, qh, ql, CE, CE, CE, CE, nullptr, nullptr);
    hmma_gemm<4,3><<<gProj, 256, SM3>>>(xh, xl, wkh, wkl, nullptr, kh, kl, CE, CE, CE, CE, nullptr, nullptr);
    hmma_gemm<0,2><<<gProj, 256, SM2>>>(xh, xl, wvh, wvl, pv, nullptr, nullptr, CE, CE, CE, CE, nullptr, nullptr);

    // 3) feature maps + denominators + z_new
    sigma2_kernel<<<gSplitBig, 256>>>((const uint2*)qh, (const uint2*)ql, (const uint2*)kh, (const uint2*)kl,
                                      (float4*)psq, (float4*)psk,
                                      (uint2*)sqh, (uint2*)sql, (uint2*)skh, (uint2*)skl);
    denom_kernel<<<dim3(CS / 8, CBH), 256>>>(psq, psk, zp, pdq, pdk);
    znew_part_kernel<<<dim3(CBH, 8), CD>>>(psk, pzpart);
    znew_final_kernel<<<CBH, CD>>>(pzpart, zp, outz);

    // 4) compressive-memory read: A_mem = (sq @ mem)/(sq.z+1e-6)  [2-term]
    hmma_gemm<5,2><<<gAM, 256, SM2>>>(sqh, sql, mth, mtl, pamem, nullptr, nullptr, CD, CE, CD, CE, pdq, nullptr);

    // 5) causal softmax attention (QK 3-term; PV 2-term with gate-mix + split out)
    hmma_gemm<2,3><<<gQK, 256, SM3>>>(qh, ql, kh, kl, pP, nullptr, nullptr, CD, CE, CE, CS, nullptr, nullptr);
    softmax_reg_kernel<<<dim3(CS / 8, CBH), 256>>>(pP, pph, ppl);
    tsplit_head_kernel<<<gTS, blkT>>>(pv, vth, vtl);
    hmma_gemm<3,2><<<gPV, 256, SM2>>>(pph, ppl, vth, vtl, nullptr, mh, ml, CS, CS, CS, CE, pamem, betas);

    // 6) memory update: U [2-term]; mem_new via split-K [3-term] + reduce
    hmma_gemm<6,2><<<gAM, 256, SM2>>>(skh, skl, mth, mtl, pU, nullptr, nullptr, CD, CE, CD, CE, pdk, pv);
    tsplit_head_kernel<<<gTS, blkT>>>(psk, skth, sktl);
    tsplit_head_kernel<<<gTS, blkT>>>(pU, uth, utl);
    hmma_gemm<10,3><<<gMU, 256, SM3>>>(skth, sktl, uth, utl, pmemp, nullptr, nullptr, 512, CS, CS, CD, nullptr, nullptr);
    memnew_reduce_kernel<<<CBH * 64, 256>>>(pmemp, memp, outmem);

    // 7) output projection + bias [2-term]
    hmma_gemm<1,2><<<gProj, 256, SM2>>>(mh, ml, woh, wol, out, nullptr, nullptr, CE, CE, CE, CE, bo, nullptr);
}

// round 15
// speedup vs baseline: 1.2357x; 1.1874x over previous
#include <cuda_runtime.h>
#include <cuda_fp16.h>
#include <cstdint>
#include <math.h>

// Problem constants
#define CB 4
#define CS 2048
#define CE 1024
#define CH 4
#define CD 256
#define CBH 16      // B*H
#define CM 8192     // B*S tokens

// ---------------- f32 scratch ----------------
__device__ float g_v   [(size_t)CM * CE];
__device__ float g_sq  [(size_t)CM * CE];
__device__ float g_sk  [(size_t)CM * CE];
__device__ float g_amem[(size_t)CM * CE];
__device__ float g_U   [(size_t)CM * CE];
__device__ float g_P   [(size_t)CBH * CS * CS];   // f32 logits
__device__ float g_denq[CBH * CS];
__device__ float g_denk[CBH * CS];
__device__ float g_zpart[CBH * 8 * CD];
__device__ float g_memp[(size_t)4 * CBH * CD * CD];  // split-K partials

// ---------------- fp16 scratch (uint4-typed for 16B alignment) ----------------
__device__ uint4 g_xh  [(size_t)CM * CE / 8];
__device__ uint4 g_xl  [(size_t)CM * CE / 8];
__device__ uint4 g_qh  [(size_t)CM * CE / 8];
__device__ uint4 g_ql  [(size_t)CM * CE / 8];
__device__ uint4 g_kh  [(size_t)CM * CE / 8];
__device__ uint4 g_kl  [(size_t)CM * CE / 8];
__device__ uint4 g_mh  [(size_t)CM * CE / 8];   // PV mix split
__device__ uint4 g_ml  [(size_t)CM * CE / 8];
__device__ uint4 g_sqh [(size_t)CM * CE / 8];
__device__ uint4 g_sql [(size_t)CM * CE / 8];
__device__ uint4 g_skh [(size_t)CM * CE / 8];
__device__ uint4 g_skl [(size_t)CM * CE / 8];
__device__ uint4 g_wqh [(size_t)CE * CE / 8];
__device__ uint4 g_wql [(size_t)CE * CE / 8];
__device__ uint4 g_wkh [(size_t)CE * CE / 8];
__device__ uint4 g_wkl [(size_t)CE * CE / 8];
__device__ uint4 g_wvh [(size_t)CE * CE / 8];
__device__ uint4 g_wvl [(size_t)CE * CE / 8];
__device__ uint4 g_woh [(size_t)CE * CE / 8];
__device__ uint4 g_wol [(size_t)CE * CE / 8];
__device__ uint4 g_ph  [(size_t)CBH * CS * CS / 8];  // softmax probs hi
__device__ uint4 g_pl  [(size_t)CBH * CS * CS / 8];  // softmax probs lo
__device__ uint4 g_vth [(size_t)CBH * CD * CS / 8];  // v^T per head
__device__ uint4 g_vtl [(size_t)CBH * CD * CS / 8];
__device__ uint4 g_skth[(size_t)CBH * CD * CS / 8];  // sk^T per head
__device__ uint4 g_sktl[(size_t)CBH * CD * CS / 8];
__device__ uint4 g_uth [(size_t)CBH * CD * CS / 8];  // U^T per head
__device__ uint4 g_utl [(size_t)CBH * CD * CS / 8];
__device__ uint4 g_mth [(size_t)CH * CD * CD / 8];   // mem^T per head
__device__ uint4 g_mtl [(size_t)CH * CD * CD / 8];

// ======================= helpers =======================
__device__ __forceinline__ uint32_t smem_u32(const void* p) {
    uint32_t a;
    asm("{ .reg .u64 t; cvta.to.shared.u64 t, %1; cvt.u32.u64 %0, t; }" : "=r"(a) : "l"(p));
    return a;
}
#define CPA16(dst, src) \
    asm volatile("cp.async.cg.shared.global [%0], [%1], 16;" :: "r"(dst), "l"(src))
#define CP_COMMIT() asm volatile("cp.async.commit_group;")
#define CP_WAIT2()  asm volatile("cp.async.wait_group 2;")

#define LDSM4(r, addr) \
    asm volatile("ldmatrix.sync.aligned.m8n8.x4.shared.b16 {%0,%1,%2,%3}, [%4];" \
        : "=r"((r)[0]), "=r"((r)[1]), "=r"((r)[2]), "=r"((r)[3]) : "r"(addr))

#define MMA16816(d, a, b0, b1) \
    asm volatile("mma.sync.aligned.m16n8k16.row.col.f32.f16.f16.f32 " \
        "{%0,%1,%2,%3}, {%4,%5,%6,%7}, {%8,%9}, {%0,%1,%2,%3};" \
        : "+f"((d)[0]), "+f"((d)[1]), "+f"((d)[2]), "+f"((d)[3]) \
        : "r"((a)[0]), "r"((a)[1]), "r"((a)[2]), "r"((a)[3]), "r"(b0), "r"(b1))

__device__ __forceinline__ __half2 split_hi2(float a, float b, __half2& lo) {
    const __half h0 = __float2half_rn(a), h1 = __float2half_rn(b);
    lo = __halves2half2(__float2half_rn(a - __half2float(h0)),
                        __float2half_rn(b - __half2float(h1)));
    return __halves2half2(h0, h1);
}

// ===========================================================================
// HMMA split-fp16 GEMM (identical to R11 winner)
// ===========================================================================
template <int EPI, int NTERM>
__global__ void __launch_bounds__(256, 1)
hmma_gemm(const __half* __restrict__ Ah, const __half* __restrict__ Al,
          const __half* __restrict__ Bh, const __half* __restrict__ Bl,
          float* __restrict__ Cg, __half* __restrict__ Oh, __half* __restrict__ Ol,
          int K, int lda, int ldb, int ldc,
          const float* __restrict__ aux0, const float* __restrict__ aux1)
{
    const int m0 = blockIdx.y * 128, n0 = blockIdx.x * 128;
    const int z = blockIdx.z;
    constexpr int SS = (NTERM == 3) ? 65536 : 49152;   // stage stride
    size_t offA = 0, offB = 0, offC = 0;
    const float* amem = nullptr;
    const float* den  = nullptr;
    const float* vsrc = nullptr;
    float gate = 0.f, omg = 0.f;
    int Keff = K;
    if (EPI == 2) {
        if (n0 >= m0 + 128) return;   // fully masked tile: softmax never reads it
        const int b = z / CH, h = z % CH;
        offA = offB = (size_t)b * CS * CE + (size_t)h * CD;
        offC = (size_t)z * CS * CS;
    } else if (EPI == 3) {
        const int b = z / CH, h = z % CH;
        offA = (size_t)z * CS * CS;
        offB = (size_t)z * CD * CS;
        offC = (size_t)b * CS * CE + (size_t)h * CD;
        amem = aux0 + offC;
        gate = 1.f / (1.f + __expf(-aux1[h]));
        omg  = 1.f - gate;
        Keff = min(K, m0 + 128);      // probs zero beyond row block
    } else if (EPI == 5 || EPI == 6) {
        const int b = z / CH, h = z % CH;
        offA = (size_t)b * CS * CE + (size_t)h * CD;
        offB = (size_t)h * CD * CD;
        offC = offA;
        den  = aux0 + (size_t)z * CS;
        if (EPI == 6) vsrc = aux1 + offC;
    } else if (EPI == 10) {
        // split-K mem-update partial: z = bh*4 + chunk, K = 512 per chunk
        const int bh = z >> 2, chunk = z & 3;
        offA = (size_t)bh * CD * CS + (size_t)chunk * 512;
        offB = offA;
        offC = (size_t)z * CD * CD;
    }

    extern __shared__ char dsm_raw[];
    char* base = dsm_raw + ((1024 - (smem_u32(dsm_raw) & 1023)) & 1023);
    const uint32_t sb = smem_u32(base);

    const int tid = threadIdx.x;
    const int wid = tid >> 5, lane = tid & 31;
    const int wm = wid & 3, wn = wid >> 2;

    const __half* pAh = Ah + offA;
    const __half* pAl = Al + offA;
    const __half* pBh = Bh + offB;
    const __half* pBl = Bl + offB;

    auto load_stage = [&](int kt, int stage) {
        const int k0 = kt * 64;
        const uint32_t sbase = sb + stage * SS;
        constexpr int NIT = (NTERM == 3) ? 16 : 12;
#pragma unroll
        for (int it = 0; it < NIT; it++) {
            const int mat = it >> 2;
            const int rem = tid + (it & 3) * 256;
            const int row = rem >> 3, k8 = rem & 7;
            const uint32_t dst = sbase + mat * 16384 + row * 128 + ((k8 ^ (row & 7)) << 4);
            const __half* src;
            if (mat == 0)      src = pAh + (size_t)(m0 + row) * lda + k0 + k8 * 8;
            else if (mat == 1) src = pAl + (size_t)(m0 + row) * lda + k0 + k8 * 8;
            else if (mat == 2) src = pBh + (size_t)(n0 + row) * ldb + k0 + k8 * 8;
            else               src = pBl + (size_t)(n0 + row) * ldb + k0 + k8 * 8;
            CPA16(dst, src);
        }
    };

    float acc[2][8][4];
#pragma unroll
    for (int mi = 0; mi < 2; mi++)
#pragma unroll
        for (int nj = 0; nj < 8; nj++)
#pragma unroll
            for (int r = 0; r < 4; r++) acc[mi][nj][r] = 0.f;

    const int nkt = Keff / 64;   // >= 2 everywhere

    load_stage(0, 0); CP_COMMIT();
    load_stage(1, 1); CP_COMMIT();
    load_stage(2, 2); CP_COMMIT();   // may prefetch past Keff: in-bounds, unused

    int buf = 0;
    for (int kt = 0; kt < nkt; kt++) {
        CP_WAIT2();
        __syncthreads();
        const uint32_t sA = sb + buf * SS;
        const uint32_t sB = sA + 32768;
#pragma unroll
        for (int ks = 0; ks < 4; ks++) {
            uint32_t af[2][2][4];
#pragma unroll
            for (int mi = 0; mi < 2; mi++) {
                const int row = wm * 32 + mi * 16 + (lane & 15);
                const int k8 = ks * 2 + (lane >> 4);
                const uint32_t off = row * 128 + ((k8 ^ (row & 7)) << 4);
                LDSM4(af[mi][0], sA + off);
                LDSM4(af[mi][1], sA + 16384 + off);
            }
            uint32_t bf[4][2][4];
#pragma unroll
            for (int np = 0; np < 4; np++) {
                const int n = wn * 64 + np * 16 + (lane & 7) + ((lane >> 4) << 3);
                const int k8 = ks * 2 + ((lane >> 3) & 1);
                const uint32_t off = n * 128 + ((k8 ^ (n & 7)) << 4);
                LDSM4(bf[np][0], sB + off);
                if (NTERM == 3) LDSM4(bf[np][1], sB + 16384 + off);
            }
#pragma unroll
            for (int mi = 0; mi < 2; mi++)
#pragma unroll
                for (int nj = 0; nj < 8; nj++) {
                    const uint32_t* bh = &bf[nj >> 1][0][(nj & 1) * 2];
                    MMA16816(acc[mi][nj], af[mi][0], bh[0], bh[1]);
                    if (NTERM == 3) {
                        const uint32_t* bl = &bf[nj >> 1][1][(nj & 1) * 2];
                        MMA16816(acc[mi][nj], af[mi][0], bl[0], bl[1]);
                    }
                    MMA16816(acc[mi][nj], af[mi][1], bh[0], bh[1]);
                }
        }
        __syncthreads();
        if (kt + 3 < nkt) load_stage(kt + 3, buf);
        CP_COMMIT();
        buf = (buf == 2) ? 0 : buf + 1;
    }

    // ---- epilogue ----
#pragma unroll
    for (int mi = 0; mi < 2; mi++) {
#pragma unroll
        for (int nj = 0; nj < 8; nj++) {
            const int gr0 = m0 + wm * 32 + mi * 16 + (lane >> 2);
            const int gc  = n0 + wn * 64 + nj * 8 + (lane & 3) * 2;
#pragma unroll
            for (int hf = 0; hf < 2; hf++) {
                const int gr = gr0 + hf * 8;
                const size_t idx = (size_t)gr * ldc + gc;
                float d0 = acc[mi][nj][hf * 2], d1 = acc[mi][nj][hf * 2 + 1];
                if (EPI == 1) { d0 += aux0[gc]; d1 += aux0[gc + 1]; }
                if (EPI == 3) {
                    d0 = gate * amem[idx] + omg * d0;
                    d1 = gate * amem[idx + 1] + omg * d1;
                }
                if (EPI == 5) {
                    const float r = 1.f / (den[gr] + 1e-6f);
                    d0 *= r; d1 *= r;
                }
                if (EPI == 6) {
                    const float r = 1.f / (den[gr] + 1e-6f);
                    d0 = vsrc[idx] - d0 * r;
                    d1 = vsrc[idx + 1] - d1 * r;
                }
                if (EPI == 3 || EPI == 4) {
                    __half2 lo;
                    const __half2 hi = split_hi2(d0, d1, lo);
                    *(__half2*)(Oh + offC + idx) = hi;
                    *(__half2*)(Ol + offC + idx) = lo;
                } else {
                    *(float2*)(Cg + offC + idx) = make_float2(d0, d1);
                }
            }
        }
    }
}

// ===========================================================================
// split / transpose-split kernels
// ===========================================================================
__global__ void split_kernel(const float4* __restrict__ in,
                             uint2* __restrict__ hi, uint2* __restrict__ lo)
{
    const size_t i = (size_t)blockIdx.x * blockDim.x + threadIdx.x;
    const float4 v = in[i];
    __half2 l0, l1;
    const __half2 h0 = split_hi2(v.x, v.y, l0);
    const __half2 h1 = split_hi2(v.z, v.w, l1);
    uint2 uh, ul;
    uh.x = *(const uint32_t*)&h0; uh.y = *(const uint32_t*)&h1;
    ul.x = *(const uint32_t*)&l0; ul.y = *(const uint32_t*)&l1;
    hi[i] = uh; lo[i] = ul;
}

// W[K,N] (1024x1024) -> Wt_hi/lo[N,K]
__global__ void splitT_kernel(const float* __restrict__ W,
                              __half* __restrict__ th, __half* __restrict__ tl)
{
    __shared__ float t[32][33];
    const int n0 = blockIdx.x * 32, k0 = blockIdx.y * 32;
    const int tx = threadIdx.x, ty = threadIdx.y;
#pragma unroll
    for (int i = 0; i < 4; i++)
        t[ty + i * 8][tx] = W[(size_t)(k0 + ty + i * 8) * CE + n0 + tx];
    __syncthreads();
#pragma unroll
    for (int i = 0; i < 4; i++) {
        const float v = t[tx][ty + i * 8];
        const __half h = __float2half_rn(v);
        const size_t o = (size_t)(n0 + ty + i * 8) * CE + k0 + tx;
        th[o] = h;
        tl[o] = __float2half_rn(v - __half2float(h));
    }
}

// src [B,S,E] head slice -> dst [bh, D, S] fp16 hi/lo (transpose + split)
__global__ void tsplit_head_kernel(const float* __restrict__ src,
                                   __half* __restrict__ th, __half* __restrict__ tl)
{
    __shared__ float t[32][33];
    const int z = blockIdx.z, b = z / CH, h = z % CH;
    const int s0 = blockIdx.x * 32, d0 = blockIdx.y * 32;
    const int tx = threadIdx.x, ty = threadIdx.y;
#pragma unroll
    for (int i = 0; i < 4; i++)
        t[ty + i * 8][tx] = src[(size_t)(b * CS + s0 + ty + i * 8) * CE + h * CD + d0 + tx];
    __syncthreads();
#pragma unroll
    for (int i = 0; i < 4; i++) {
        const float vv = t[tx][ty + i * 8];
        const __half hh = __float2half_rn(vv);
        const size_t o = ((size_t)z * CD + d0 + ty + i * 8) * CS + s0 + tx;
        th[o] = hh;
        tl[o] = __float2half_rn(vv - __half2float(hh));
    }
}

// mem [H,D,D] -> memT [h, e, d] fp16 hi/lo
__global__ void memT_kernel(const float* __restrict__ mem,
                            __half* __restrict__ th, __half* __restrict__ tl)
{
    __shared__ float t[32][33];
    const int h = blockIdx.z;
    const int d0 = blockIdx.x * 32, e0 = blockIdx.y * 32;
    const int tx = threadIdx.x, ty = threadIdx.y;
#pragma unroll
    for (int i = 0; i < 4; i++)
        t[ty + i * 8][tx] = mem[(size_t)h * CD * CD + (size_t)(d0 + ty + i * 8) * CD + e0 + tx];
    __syncthreads();
#pragma unroll
    for (int i = 0; i < 4; i++) {
        const float v = t[tx][ty + i * 8];     // mem[d0+tx][e0+ty+i*8]
        const __half hh = __float2half_rn(v);
        const size_t o = (size_t)h * CD * CD + (size_t)(e0 + ty + i * 8) * CD + d0 + tx;
        th[o] = hh;
        tl[o] = __float2half_rn(v - __half2float(hh));
    }
}

// sigma for ONE tensor: s = elu(hi+lo)+1; writes f32 + split fp16
__global__ void sigma1_kernel(const uint2* __restrict__ xhp, const uint2* __restrict__ xlp,
                              float4* __restrict__ sf,
                              uint2* __restrict__ sh, uint2* __restrict__ sl)
{
    const size_t i = (size_t)blockIdx.x * blockDim.x + threadIdx.x;
    const uint2 h = xhp[i], l = xlp[i];
    const __half2 h0 = *(const __half2*)&h.x, h1 = *(const __half2*)&h.y;
    const __half2 l0 = *(const __half2*)&l.x, l1 = *(const __half2*)&l.y;
    float x[4];
    x[0] = __half2float(h0.x) + __half2float(l0.x);
    x[1] = __half2float(h0.y) + __half2float(l0.y);
    x[2] = __half2float(h1.x) + __half2float(l1.x);
    x[3] = __half2float(h1.y) + __half2float(l1.y);
#pragma unroll
    for (int j = 0; j < 4; j++) x[j] = (x[j] > 0.f) ? x[j] + 1.f : __expf(x[j]);
    sf[i] = make_float4(x[0], x[1], x[2], x[3]);
    __half2 o0, o1;
    const __half2 p0 = split_hi2(x[0], x[1], o0);
    const __half2 p1 = split_hi2(x[2], x[3], o1);
    uint2 uh, ul;
    uh.x = *(const uint32_t*)&p0; uh.y = *(const uint32_t*)&p1;
    ul.x = *(const uint32_t*)&o0; ul.y = *(const uint32_t*)&o1;
    sh[i] = uh; sl[i] = ul;
}

// den[bh][s] = sigma[row] . z_h  (one tensor). One warp per row.
__global__ void denom1_kernel(const float* __restrict__ sv, const float* __restrict__ zv,
                              float* __restrict__ den)
{
    const int z = blockIdx.y;
    const int b = z / CH, h = z % CH;
    const int warp = threadIdx.x >> 5, lane = threadIdx.x & 31;
    const int s = blockIdx.x * 8 + warp;
    const size_t base = (size_t)(b * CS + s) * CE + (size_t)h * CD;
    const float* zp = zv + h * CD;
    float a = 0.f;
#pragma unroll
    for (int d = lane; d < CD; d += 32)
        a = fmaf(sv[base + d], zp[d], a);
#pragma unroll
    for (int o = 16; o > 0; o >>= 1)
        a += __shfl_xor_sync(0xffffffffu, a, o);
    if (lane == 0) den[z * CS + s] = a;
}

// z_new partials: grid (CBH, 8); each chunk sums 256 rows
__global__ void znew_part_kernel(const float* __restrict__ sk, float* __restrict__ part)
{
    const int z = blockIdx.x, chunk = blockIdx.y;
    const int b = z / CH, h = z % CH;
    const int d = threadIdx.x;
    const float* p = sk + (size_t)(b * CS + chunk * 256) * CE + (size_t)h * CD + d;
    float sum = 0.f;
    for (int s = 0; s < 256; s += 8) {
        float t = 0.f;
#pragma unroll
        for (int u = 0; u < 8; u++) t += p[(size_t)(s + u) * CE];
        sum += t;
    }
    part[((size_t)z * 8 + chunk) * CD + d] = sum;
}

__global__ void znew_final_kernel(const float* __restrict__ part,
                                  const float* __restrict__ zv, float* __restrict__ outz)
{
    const int z = blockIdx.x;
    const int d = threadIdx.x;
    float sum = zv[(z % CH) * CD + d];
#pragma unroll
    for (int c = 0; c < 8; c++) sum += part[((size_t)z * 8 + c) * CD + d];
    outz[(size_t)z * CD + d] = sum;
}

// mem_new reduce: out = mem + sum of 4 split-K partials. grid CBH*64, 256 thr.
__global__ void memnew_reduce_kernel(const float* __restrict__ part,
                                     const float* __restrict__ mem, float* __restrict__ outm)
{
    const int z = blockIdx.x >> 6;               // bh
    const int blk = blockIdx.x & 63;
    const size_t e = (size_t)blk * 1024 + threadIdx.x * 4;
    const size_t bo = (size_t)z * CD * CD + e;
    float4 s = *(const float4*)(mem + (size_t)(z % CH) * CD * CD + e);
#pragma unroll
    for (int c = 0; c < 4; c++) {
        const float4 p = *(const float4*)(part + ((size_t)(z * 4 + c)) * CD * CD + e);
        s.x += p.x; s.y += p.y; s.z += p.z; s.w += p.w;
    }
    *(float4*)(outm + bo) = s;
}

// register-resident causal softmax: one warp per row, prefix tiles only
__global__ void __launch_bounds__(256)
softmax_reg_kernel(const float* __restrict__ P,
                   __half* __restrict__ oh, __half* __restrict__ ol)
{
    const int z = blockIdx.y;
    const int warp = threadIdx.x >> 5, lane = threadIdx.x & 31;
    const int row = blockIdx.x * 8 + warp;
    const size_t off = (size_t)z * CS * CS + (size_t)row * CS;
    const float4* p4 = (const float4*)(P + off);
    const int len = row + 1;
    const int ntiles = (row >> 7) + 1;   // 128-col tiles containing the prefix

    float v[64];
#pragma unroll
    for (int i = 0; i < 16; i++) {
        if (i < ntiles)
            *(float4*)(v + i * 4) = p4[i * 32 + lane];
        else {
            v[i * 4] = v[i * 4 + 1] = v[i * 4 + 2] = v[i * 4 + 3] = -3.0e38f;
        }
    }

    float m = -3.0e38f;
#pragma unroll
    for (int i = 0; i < 16; i++) {
        const int c = i * 128 + lane * 4;
#pragma unroll
        for (int j = 0; j < 4; j++) {
            if (c + j >= len) v[i * 4 + j] = -3.0e38f;
            m = fmaxf(m, v[i * 4 + j]);
        }
    }
#pragma unroll
    for (int o = 16; o > 0; o >>= 1) m = fmaxf(m, __shfl_xor_sync(0xffffffffu, m, o));

    float sum = 0.f;
#pragma unroll
    for (int i = 0; i < 64; i++) {
        v[i] = __expf(v[i] - m);       // masked -> exp(-huge) = 0
        sum += v[i];
    }
#pragma unroll
    for (int o = 16; o > 0; o >>= 1) sum += __shfl_xor_sync(0xffffffffu, sum, o);
    const float inv = 1.f / sum;

    __half* ph = oh + off;
    __half* pl = ol + off;
#pragma unroll
    for (int i = 0; i < 16; i++) {
        if (i >= ntiles) continue;     // PV never reads beyond the prefix tiles
        const int c = i * 128 + lane * 4;
        __half2 l0, l1;
        const __half2 h0 = split_hi2(v[i * 4] * inv, v[i * 4 + 1] * inv, l0);
        const __half2 h1 = split_hi2(v[i * 4 + 2] * inv, v[i * 4 + 3] * inv, l1);
        uint2 uh, ul;
        uh.x = *(const uint32_t*)&h0; uh.y = *(const uint32_t*)&h1;
        ul.x = *(const uint32_t*)&l0; ul.y = *(const uint32_t*)&l1;
        *(uint2*)(ph + c) = uh;
        *(uint2*)(pl + c) = ul;
    }
}

// ===========================================================================
extern "C" void kernel_launch(void* const* d_in, const int* in_sizes, int n_in,
                              void* d_out, int out_size)
{
    (void)in_sizes; (void)n_in; (void)out_size;
    const float* X     = (const float*)d_in[0];
    const float* Wq    = (const float*)d_in[1];
    const float* Wk    = (const float*)d_in[2];
    const float* Wv    = (const float*)d_in[3];
    const float* Wo    = (const float*)d_in[4];
    const float* bo    = (const float*)d_in[5];
    const float* betas = (const float*)d_in[6];
    const float* memp  = (const float*)d_in[7];
    const float* zp    = (const float*)d_in[8];
    float* out = (float*)d_out;

    // ---- one-time stream/event setup (host-side objects only) ----
    static cudaStream_t s1 = nullptr, s2 = nullptr;
    static cudaEvent_t e0, eXs, eW, eMT, eQ, eK, eV, eVT, eAM, eSK, j1, j2;
    if (s1 == nullptr) {
        cudaStreamCreateWithFlags(&s1, cudaStreamNonBlocking);
        cudaStreamCreateWithFlags(&s2, cudaStreamNonBlocking);
        cudaEventCreateWithFlags(&e0,  cudaEventDisableTiming);
        cudaEventCreateWithFlags(&eXs, cudaEventDisableTiming);
        cudaEventCreateWithFlags(&eW,  cudaEventDisableTiming);
        cudaEventCreateWithFlags(&eMT, cudaEventDisableTiming);
        cudaEventCreateWithFlags(&eQ,  cudaEventDisableTiming);
        cudaEventCreateWithFlags(&eK,  cudaEventDisableTiming);
        cudaEventCreateWithFlags(&eV,  cudaEventDisableTiming);
        cudaEventCreateWithFlags(&eVT, cudaEventDisableTiming);
        cudaEventCreateWithFlags(&eAM, cudaEventDisableTiming);
        cudaEventCreateWithFlags(&eSK, cudaEventDisableTiming);
        cudaEventCreateWithFlags(&j1,  cudaEventDisableTiming);
        cudaEventCreateWithFlags(&j2,  cudaEventDisableTiming);
    }
    cudaStream_t s0 = 0;

    float *pv, *psq, *psk, *pamem, *pU, *pP, *pdq, *pdk, *pzpart, *pmemp;
    cudaGetSymbolAddress((void**)&pv,    g_v);
    cudaGetSymbolAddress((void**)&psq,   g_sq);
    cudaGetSymbolAddress((void**)&psk,   g_sk);
    cudaGetSymbolAddress((void**)&pamem, g_amem);
    cudaGetSymbolAddress((void**)&pU,    g_U);
    cudaGetSymbolAddress((void**)&pP,    g_P);
    cudaGetSymbolAddress((void**)&pdq,   g_denq);
    cudaGetSymbolAddress((void**)&pdk,   g_denk);
    cudaGetSymbolAddress((void**)&pzpart, g_zpart);
    cudaGetSymbolAddress((void**)&pmemp, g_memp);

    __half *xh, *xl, *qh, *ql, *kh, *kl, *mh, *ml;
    __half *sqh, *sql, *skh, *skl;
    __half *wqh, *wql, *wkh, *wkl, *wvh, *wvl, *woh, *wol;
    __half *pph, *ppl, *vth, *vtl, *skth, *sktl, *uth, *utl, *mth, *mtl;
    cudaGetSymbolAddress((void**)&xh,   g_xh);   cudaGetSymbolAddress((void**)&xl,   g_xl);
    cudaGetSymbolAddress((void**)&qh,   g_qh);   cudaGetSymbolAddress((void**)&ql,   g_ql);
    cudaGetSymbolAddress((void**)&kh,   g_kh);   cudaGetSymbolAddress((void**)&kl,   g_kl);
    cudaGetSymbolAddress((void**)&mh,   g_mh);   cudaGetSymbolAddress((void**)&ml,   g_ml);
    cudaGetSymbolAddress((void**)&sqh,  g_sqh);  cudaGetSymbolAddress((void**)&sql,  g_sql);
    cudaGetSymbolAddress((void**)&skh,  g_skh);  cudaGetSymbolAddress((void**)&skl,  g_skl);
    cudaGetSymbolAddress((void**)&wqh,  g_wqh);  cudaGetSymbolAddress((void**)&wql,  g_wql);
    cudaGetSymbolAddress((void**)&wkh,  g_wkh);  cudaGetSymbolAddress((void**)&wkl,  g_wkl);
    cudaGetSymbolAddress((void**)&wvh,  g_wvh);  cudaGetSymbolAddress((void**)&wvl,  g_wvl);
    cudaGetSymbolAddress((void**)&woh,  g_woh);  cudaGetSymbolAddress((void**)&wol,  g_wol);
    cudaGetSymbolAddress((void**)&pph,  g_ph);   cudaGetSymbolAddress((void**)&ppl,  g_pl);
    cudaGetSymbolAddress((void**)&vth,  g_vth);  cudaGetSymbolAddress((void**)&vtl,  g_vtl);
    cudaGetSymbolAddress((void**)&skth, g_skth); cudaGetSymbolAddress((void**)&sktl, g_sktl);
    cudaGetSymbolAddress((void**)&uth,  g_uth);  cudaGetSymbolAddress((void**)&utl,  g_utl);
    cudaGetSymbolAddress((void**)&mth,  g_mth);  cudaGetSymbolAddress((void**)&mtl,  g_mtl);

    const int SM3 = 3 * 65536 + 1024;
    const int SM2 = 3 * 49152 + 1024;
    cudaFuncSetAttribute(hmma_gemm<4,3>,  cudaFuncAttributeMaxDynamicSharedMemorySize, SM3);
    cudaFuncSetAttribute(hmma_gemm<2,3>,  cudaFuncAttributeMaxDynamicSharedMemorySize, SM3);
    cudaFuncSetAttribute(hmma_gemm<10,3>, cudaFuncAttributeMaxDynamicSharedMemorySize, SM3);
    cudaFuncSetAttribute(hmma_gemm<0,2>,  cudaFuncAttributeMaxDynamicSharedMemorySize, SM2);
    cudaFuncSetAttribute(hmma_gemm<1,2>,  cudaFuncAttributeMaxDynamicSharedMemorySize, SM2);
    cudaFuncSetAttribute(hmma_gemm<3,2>,  cudaFuncAttributeMaxDynamicSharedMemorySize, SM2);
    cudaFuncSetAttribute(hmma_gemm<5,2>,  cudaFuncAttributeMaxDynamicSharedMemorySize, SM2);
    cudaFuncSetAttribute(hmma_gemm<6,2>,  cudaFuncAttributeMaxDynamicSharedMemorySize, SM2);

    const dim3 blkT(32, 8);
    const dim3 gSplitBig((unsigned)((size_t)CM * CE / 4 / 256));
    const dim3 gSplitW(CE / 32, CE / 32);
    const dim3 gProj(CE / 128, CM / 128, 1);     // 8 x 64
    const dim3 gQK(CS / 128, CS / 128, CBH);     // 16 x 16 x 16
    const dim3 gPV(CD / 128, CS / 128, CBH);     // 2 x 16 x 16
    const dim3 gAM(CD / 128, CS / 128, CBH);     // 2 x 16 x 16
    const dim3 gMU(CD / 128, CD / 128, CBH * 4); // 2 x 2 x 64 (split-K)
    const dim3 gTS(CS / 32, CD / 32, CBH);
    const dim3 gMT(CD / 32, CD / 32, CH);
    float* outmem = out + (size_t)CM * CE;
    float* outz   = outmem + (size_t)CBH * CD * CD;

    // ---- fork ----
    cudaEventRecord(e0, s0);
    cudaStreamWaitEvent(s1, e0, 0);
    cudaStreamWaitEvent(s2, e0, 0);

    // S0: X split + Wq/Wk splits
    split_kernel<<<gSplitBig, 256, 0, s0>>>((const float4*)X, (uint2*)xh, (uint2*)xl);
    cudaEventRecord(eXs, s0);
    splitT_kernel<<<gSplitW, blkT, 0, s0>>>(Wq, wqh, wql);
    splitT_kernel<<<gSplitW, blkT, 0, s0>>>(Wk, wkh, wkl);

    // S1: Wv/Wo splits
    splitT_kernel<<<gSplitW, blkT, 0, s1>>>(Wv, wvh, wvl);
    splitT_kernel<<<gSplitW, blkT, 0, s1>>>(Wo, woh, wol);
    cudaEventRecord(eW, s1);

    // S2: memT
    memT_kernel<<<gMT, blkT, 0, s2>>>(memp, mth, mtl);
    cudaEventRecord(eMT, s2);

    // S0: Q projection
    hmma_gemm<4,3><<<gProj, 256, SM3, s0>>>(xh, xl, wqh, wql, nullptr, qh, ql, CE, CE, CE, CE, nullptr, nullptr);
    cudaEventRecord(eQ, s0);

    // S1: V projection + v^T split
    cudaStreamWaitEvent(s1, eXs, 0);
    hmma_gemm<0,2><<<gProj, 256, SM2, s1>>>(xh, xl, wvh, wvl, pv, nullptr, nullptr, CE, CE, CE, CE, nullptr, nullptr);
    cudaEventRecord(eV, s1);
    tsplit_head_kernel<<<gTS, blkT, 0, s1>>>(pv, vth, vtl);
    cudaEventRecord(eVT, s1);

    // S2: sigma_q -> denom_q -> A_mem
    cudaStreamWaitEvent(s2, eQ, 0);
    sigma1_kernel<<<gSplitBig, 256, 0, s2>>>((const uint2*)qh, (const uint2*)ql, (float4*)psq, (uint2*)sqh, (uint2*)sql);
    denom1_kernel<<<dim3(CS / 8, CBH), 256, 0, s2>>>(psq, zp, pdq);
    hmma_gemm<5,2><<<gAM, 256, SM2, s2>>>(sqh, sql, mth, mtl, pamem, nullptr, nullptr, CD, CE, CD, CE, pdq, nullptr);
    cudaEventRecord(eAM, s2);

    // S0: K projection
    hmma_gemm<4,3><<<gProj, 256, SM3, s0>>>(xh, xl, wkh, wkl, nullptr, kh, kl, CE, CE, CE, CE, nullptr, nullptr);
    cudaEventRecord(eK, s0);

    // S2: sigma_k -> denom_k -> U -> transposes -> mem update
    cudaStreamWaitEvent(s2, eK, 0);
    sigma1_kernel<<<gSplitBig, 256, 0, s2>>>((const uint2*)kh, (const uint2*)kl, (float4*)psk, (uint2*)skh, (uint2*)skl);
    cudaEventRecord(eSK, s2);
    denom1_kernel<<<dim3(CS / 8, CBH), 256, 0, s2>>>(psk, zp, pdk);
    cudaStreamWaitEvent(s2, eV, 0);
    hmma_gemm<6,2><<<gAM, 256, SM2, s2>>>(skh, skl, mth, mtl, pU, nullptr, nullptr, CD, CE, CD, CE, pdk, pv);
    tsplit_head_kernel<<<gTS, blkT, 0, s2>>>(psk, skth, sktl);
    tsplit_head_kernel<<<gTS, blkT, 0, s2>>>(pU, uth, utl);
    hmma_gemm<10,3><<<gMU, 256, SM3, s2>>>(skth, sktl, uth, utl, pmemp, nullptr, nullptr, 512, CS, CS, CD, nullptr, nullptr);
    memnew_reduce_kernel<<<CBH * 64, 256, 0, s2>>>(pmemp, memp, outmem);
    cudaEventRecord(j2, s2);

    // S1: z_new chain
    cudaStreamWaitEvent(s1, eSK, 0);
    znew_part_kernel<<<dim3(CBH, 8), CD, 0, s1>>>(psk, pzpart);
    znew_final_kernel<<<CBH, CD, 0, s1>>>(pzpart, zp, outz);
    cudaEventRecord(j1, s1);

    // S0: QK -> softmax -> PV -> O projection
    hmma_gemm<2,3><<<gQK, 256, SM3, s0>>>(qh, ql, kh, kl, pP, nullptr, nullptr, CD, CE, CE, CS, nullptr, nullptr);
    softmax_reg_kernel<<<dim3(CS / 8, CBH), 256, 0, s0>>>(pP, pph, ppl);
    cudaStreamWaitEvent(s0, eVT, 0);
    cudaStreamWaitEvent(s0, eAM, 0);
    hmma_gemm<3,2><<<gPV, 256, SM2, s0>>>(pph, ppl, vth, vtl, nullptr, mh, ml, CS, CS, CS, CE, pamem, betas);
    cudaStreamWaitEvent(s0, eW, 0);
    hmma_gemm<1,2><<<gProj, 256, SM2, s0>>>(mh, ml, woh, wol, out, nullptr, nullptr, CE, CE, CE, CE, bo, nullptr);

    // ---- join ----
    cudaStreamWaitEvent(s0, j1, 0);
    cudaStreamWaitEvent(s0, j2, 0);
}